// round 11
// baseline (speedup 1.0000x reference)
#include <cuda_runtime.h>
#include <cuda_bf16.h>
#include <cstdint>

typedef unsigned long long u64;

// ---------------------------------------------------------------------------
// dilate_block — round 11: R10 base plus line-cooperative gather:
//   8 lanes read one 128B line of one row together -> gather L1 wavefronts /4
//   row indices distributed via __shfl_sync (1 nbr load per tap)
// ---------------------------------------------------------------------------

static constexpr int MAXR = 640000;
static constexpr int MAXBLK = MAXR / 128 + 2;

__device__ __align__(16) float g_A [MAXR * 64];
__device__ __align__(16) float g_B [MAXR * 64];
__device__ __align__(16) float g_C [MAXR * 64];
__device__ __align__(16) float g_X1[MAXR * 64];
__device__ __align__(16) float g_X2[MAXR * 64];
__device__ __align__(16) float g_X3[MAXR * 64];
__device__ float g_pS[MAXBLK * 64];
__device__ float g_pQ[MAXBLK * 64];
__device__ float g_st[4 * 128];
__device__ unsigned g_tick;                             // zero-init, self-resetting
__device__ __align__(16) float g_Wt[3 * 4096];          // down_w packed (fp32 path)
__device__ __align__(16) uint32_t g_Wb[516096];         // conv weights, frag-major, hi/lo interleaved

// ---------------- helpers ----------------
__device__ __forceinline__ uint32_t smem_u32(const void* p) {
    uint32_t a;
    asm("{ .reg .u64 t; cvta.to.shared.u64 t, %1; cvt.u32.u64 %0, t; }" : "=r"(a) : "l"(p));
    return a;
}
__device__ __forceinline__ uint32_t cvt2(float lo, float hi) {
    uint32_t r;
    asm("cvt.rn.bf16x2.f32 %0, %1, %2;" : "=r"(r) : "f"(hi), "f"(lo));
    return r;
}
__device__ __forceinline__ uint32_t lds32(uint32_t a) {
    uint32_t v;
    asm volatile("ld.shared.b32 %0, [%1];" : "=r"(v) : "r"(a));
    return v;
}
__device__ __forceinline__ void st32(uint32_t a, uint32_t v) {
    asm volatile("st.shared.b32 [%0], %1;" :: "r"(a), "r"(v));
}
__device__ __forceinline__ void mma_bf16(float d[4], const uint32_t a[4], const uint32_t b[2]) {
    asm volatile(
        "mma.sync.aligned.m16n8k16.row.col.f32.bf16.bf16.f32 "
        "{%0,%1,%2,%3}, {%4,%5,%6,%7}, {%8,%9}, {%0,%1,%2,%3};"
        : "+f"(d[0]), "+f"(d[1]), "+f"(d[2]), "+f"(d[3])
        : "r"(a[0]), "r"(a[1]), "r"(a[2]), "r"(a[3]), "r"(b[0]), "r"(b[1]));
}
__device__ __forceinline__ u64 ffma2(u64 a, u64 b, u64 c) {
    u64 d;
    asm("fma.rn.f32x2 %0, %1, %2, %3;" : "=l"(d) : "l"(a), "l"(b), "l"(c));
    return d;
}

// ---------------------------------------------------------------------------
// weight prep: fp32 [K][CIN][64] -> per tap [kt][nt(8)][lane(32)][hi0,hi1,lo0,lo1]
// ---------------------------------------------------------------------------
struct WPtrs { const float* p[13]; };

__global__ void __launch_bounds__(256)
wprep(WPtrs w, uint32_t* __restrict__ dst)
{
    const int nT[13]   = {9,9,9,9,27,9,9,9,9,9,9,9,9};
    const int cinA[13] = {32,64,32,64,64,64,64,64,64,64,64,64,64};
    const int offW[13] = {0,18432,55296,73728,110592,221184,258048,294912,
                          331776,368640,405504,442368,479232};
    int b = blockIdx.x, c = 0;
    while (b >= nT[c]) { b -= nT[c]; ++c; }
    const int CIN = cinA[c];
    const int KT = CIN / 16;
    const float* src = w.p[c] + (size_t)b * CIN * 64;
    uint16_t* tap = reinterpret_cast<uint16_t*>(dst + offW[c] + (size_t)b * (KT * 1024));
    for (int e = threadIdx.x; e < CIN * 64; e += 256) {
        const int ci = e >> 6, co = e & 63;
        const float x = src[e];
        __nv_bfloat16 hb = __float2bfloat16(x);
        __nv_bfloat16 lb = __float2bfloat16(x - __bfloat162float(hb));
        const int kt = ci >> 4, ck = (ci & 15) >> 1, j = ci & 1;
        const int regb = (ck >= 4) ? 1 : 0;
        const int tt = ck & 3, nt = co >> 3, gg = co & 7;
        const int word = (((kt * 8 + nt) * 32 + (gg * 4 + tt)) * 4) + regb;  // hi at +0/+1
        tap[word * 2 + j]       = *reinterpret_cast<unsigned short*>(&hb);
        tap[(word + 2) * 2 + j] = *reinterpret_cast<unsigned short*>(&lb);   // lo at +2/+3
    }
}

__global__ void wtrans_down(const float* __restrict__ src, float* __restrict__ dst)
{
    const int k = blockIdx.x;
    for (int e = threadIdx.x; e < 4096; e += 256) {
        const int ci = e >> 6, co = e & 63;
        dst[k * 4096 + ((ci >> 2) * 64 + co) * 4 + (ci & 3)] = src[k * 4096 + e];
    }
}

// ---------------------------------------------------------------------------
// mma.sync gather-GEMM conv. 256 thr, 8 warps x 16 rows = 128 rows per block.
// Line-cooperative gather; fused input BN (BN) and output stats (STATS).
// ---------------------------------------------------------------------------
template <int KTILES, int KTAPS, bool STATS, bool BN>
__global__ void __launch_bounds__(256, 2)
mma_conv(const float* __restrict__ in, int nIn,
         const int* __restrict__ nbr, int nOut,
         const uint32_t* __restrict__ Wg,
         float* __restrict__ out,
         float* __restrict__ pSum, float* __restrict__ pSq,
         float* __restrict__ stOut, const float* __restrict__ bnIn)
{
    constexpr int CIN = KTILES * 16;
    constexpr int TAPW = KTILES * 1024;              // b32 words per tap
    constexpr int ATERM_BYTES = KTILES * 4 * 33 * 4; // stride-33 padded frag layout
    constexpr int ABUF_BYTES = 2 * ATERM_BYTES;
    constexpr int NF4 = CIN / 8;                     // gather iterations per lane

    extern __shared__ __align__(16) char smem[];
    __shared__ float redS[8][64];
    __shared__ float redQ[8][64];
    __shared__ float s_st[128];
    __shared__ unsigned s_last;

    const uint32_t abase = smem_u32(smem);
    const int t = threadIdx.x;
    const int w = t >> 5;
    const int l = t & 31;
    const int rowBase = blockIdx.x * 128 + w * 16;

    if (BN) {
        if (t < 128) s_st[t] = bnIn[t];
        __syncthreads();
    }

    const uint32_t abuf0 = abase + (uint32_t)(w * 2 + 0) * ABUF_BYTES;
    const uint32_t abuf1 = abase + (uint32_t)(w * 2 + 1) * ABUF_BYTES;

    // line-cooperative gather: iteration i covers 4 lines; lane l reads 16B of
    // unit u = (l>>3) + 4i at byte offset (l&7)*16 within the line.
    //   CIN==64: unit = (row, half-line);  CIN==32: unit = row.
    float4 pf[NF4];
    auto prefetch = [&](int k) {
        int jr = nIn;
        if (l < 16 && rowBase + l < nOut) jr = __ldg(&nbr[(size_t)k * nOut + rowBase + l]);
#pragma unroll
        for (int i = 0; i < NF4; ++i) {
            const int u = (l >> 3) + 4 * i;
            const int row = (CIN == 64) ? (u >> 1) : u;
            const int half = (CIN == 64) ? (u & 1) : 0;
            const int c4 = half * 32 + (l & 7) * 4;
            const int j = __shfl_sync(0xFFFFFFFFu, jr, row);
            if (j < nIn) {
                float4 v = *reinterpret_cast<const float4*>(in + (size_t)j * CIN + c4);
                if (BN) {
                    v.x = (v.x - s_st[c4 + 0]) * s_st[64 + c4 + 0];
                    v.y = (v.y - s_st[c4 + 1]) * s_st[64 + c4 + 1];
                    v.z = (v.z - s_st[c4 + 2]) * s_st[64 + c4 + 2];
                    v.w = (v.w - s_st[c4 + 3]) * s_st[64 + c4 + 3];
                    v.x = v.x > 0.f ? v.x : 0.01f * v.x;
                    v.y = v.y > 0.f ? v.y : 0.01f * v.y;
                    v.z = v.z > 0.f ? v.z : 0.01f * v.z;
                    v.w = v.w > 0.f ? v.w : 0.01f * v.w;
                }
                pf[i] = v;
            } else {
                pf[i] = make_float4(0.f, 0.f, 0.f, 0.f);
            }
        }
    };
    auto convert_sts = [&](uint32_t buf) {
#pragma unroll
        for (int i = 0; i < NF4; ++i) {
            const int u = (l >> 3) + 4 * i;
            const int row = (CIN == 64) ? (u >> 1) : u;
            const int half = (CIN == 64) ? (u & 1) : 0;
            const int c4 = half * 32 + (l & 7) * 4;
            const int kt = c4 >> 4;
            const int q = c4 & 15;                       // 0,4,8,12
            const int regb = (row >> 3) | ((q & 8) ? 2 : 0);
            const int lane0 = ((row & 7) << 2) + ((q & 4) ? 2 : 0);
            const uint32_t w0 = (uint32_t)(((kt * 4 + regb) * 33 + lane0) * 4);
            const float4 x = pf[i];
            const uint32_t h0 = cvt2(x.x, x.y);
            const uint32_t h1 = cvt2(x.z, x.w);
            const float l0 = x.x - __uint_as_float(h0 << 16);
            const float l1 = x.y - __uint_as_float(h0 & 0xFFFF0000u);
            const float l2 = x.z - __uint_as_float(h1 << 16);
            const float l3 = x.w - __uint_as_float(h1 & 0xFFFF0000u);
            const uint32_t q0 = cvt2(l0, l1);
            const uint32_t q1 = cvt2(l2, l3);
            st32(buf + w0, h0);
            st32(buf + w0 + 4, h1);
            st32(buf + ATERM_BYTES + w0, q0);
            st32(buf + ATERM_BYTES + w0 + 4, q1);
        }
    };

    float acc[8][4];
#pragma unroll
    for (int nt = 0; nt < 8; ++nt)
#pragma unroll
        for (int j = 0; j < 4; ++j) acc[nt][j] = 0.f;

    prefetch(0);
    convert_sts(abuf0);
    __syncwarp();

    for (int k = 0; k < KTAPS; ++k) {
        const uint32_t cur = (k & 1) ? abuf1 : abuf0;
        const uint32_t nxt = (k & 1) ? abuf0 : abuf1;
        if (k + 1 < KTAPS) prefetch(k + 1);
        const uint32_t* wtap = Wg + (size_t)k * TAPW;
#pragma unroll
        for (int kt = 0; kt < KTILES; ++kt) {
            uint32_t ah[4], al[4];
#pragma unroll
            for (int j = 0; j < 4; ++j) {
                const uint32_t ao = (uint32_t)(((kt * 4 + j) * 33 + l) * 4);
                ah[j] = lds32(cur + ao);
                al[j] = lds32(cur + ATERM_BYTES + ao);
            }
#pragma unroll
            for (int nt = 0; nt < 8; ++nt) {
                const uint32_t widx = ((kt * 8 + nt) * 32 + l) * 4;
                const uint4 bv = __ldg(reinterpret_cast<const uint4*>(wtap + widx));
                uint32_t bh[2] = {bv.x, bv.y};
                uint32_t bl[2] = {bv.z, bv.w};
                mma_bf16(acc[nt], ah, bh);
                mma_bf16(acc[nt], al, bh);
                mma_bf16(acc[nt], ah, bl);
            }
        }
        if (k + 1 < KTAPS) convert_sts(nxt);
        __syncwarp();
    }

    // ---- epilogue: write D fragments ----
    const int dg = l >> 2, dt = l & 3;
    const int row0 = rowBase + dg;
    const int row1 = row0 + 8;
    if (row0 < nOut) {
        float* o = out + (size_t)row0 * 64 + dt * 2;
#pragma unroll
        for (int nt = 0; nt < 8; ++nt)
            *reinterpret_cast<float2*>(o + nt * 8) = make_float2(acc[nt][0], acc[nt][1]);
    }
    if (row1 < nOut) {
        float* o = out + (size_t)row1 * 64 + dt * 2;
#pragma unroll
        for (int nt = 0; nt < 8; ++nt)
            *reinterpret_cast<float2*>(o + nt * 8) = make_float2(acc[nt][2], acc[nt][3]);
    }

    if (STATS) {
#pragma unroll
        for (int nt = 0; nt < 8; ++nt) {
#pragma unroll
            for (int j = 0; j < 2; ++j) {
                float ss = acc[nt][j] + acc[nt][j + 2];
                float qq = acc[nt][j] * acc[nt][j] + acc[nt][j + 2] * acc[nt][j + 2];
                ss += __shfl_xor_sync(0xFFFFFFFFu, ss, 4);
                qq += __shfl_xor_sync(0xFFFFFFFFu, qq, 4);
                ss += __shfl_xor_sync(0xFFFFFFFFu, ss, 8);
                qq += __shfl_xor_sync(0xFFFFFFFFu, qq, 8);
                ss += __shfl_xor_sync(0xFFFFFFFFu, ss, 16);
                qq += __shfl_xor_sync(0xFFFFFFFFu, qq, 16);
                if (l < 4) {
                    redS[w][nt * 8 + l * 2 + j] = ss;
                    redQ[w][nt * 8 + l * 2 + j] = qq;
                }
            }
        }
        __syncthreads();
        if (t < 64) {
            float s = 0.f, q = 0.f;
#pragma unroll
            for (int ww = 0; ww < 8; ++ww) { s += redS[ww][t]; q += redQ[ww][t]; }
            pSum[(size_t)blockIdx.x * 64 + t] = s;
            pSq [(size_t)blockIdx.x * 64 + t] = q;
        }
        __syncthreads();
        __threadfence();
        if (t == 0) s_last = (atomicAdd(&g_tick, 1u) == gridDim.x - 1u) ? 1u : 0u;
        __syncthreads();
        if (s_last) {
            __threadfence();
            const int co = t & 63, sub = t >> 6;
            float s = 0.f, q = 0.f;
            for (int b = sub; b < (int)gridDim.x; b += 4) {
                s += pSum[(size_t)b * 64 + co];
                q += pSq[(size_t)b * 64 + co];
            }
            redS[sub][co] = s;
            redQ[sub][co] = q;
            __syncthreads();
            if (t < 64) {
                const float S = (redS[0][t] + redS[1][t]) + (redS[2][t] + redS[3][t]);
                const float Q = (redQ[0][t] + redQ[1][t]) + (redQ[2][t] + redQ[3][t]);
                const float inv = 1.0f / (float)nOut;
                const float m = S * inv;
                const float var = Q * inv - m * m;
                stOut[t] = m;
                stOut[64 + t] = rsqrtf(var + 1e-5f);
            }
            __syncthreads();
            if (t == 0) g_tick = 0u;
        }
    }
}

// ---------------------------------------------------------------------------
__global__ void combine_kernel(const float4* __restrict__ a, const float* __restrict__ sa,
                               const float4* __restrict__ b, const float* __restrict__ sb,
                               float4* __restrict__ o, long long n4)
{
    const long long i = (long long)blockIdx.x * blockDim.x + threadIdx.x;
    if (i >= n4) return;
    const int c = ((int)(i & 15)) * 4;
    float4 va = a[i];
    float4 vb = b[i];
    float4 r;
    float x;
    x = (va.x - sa[c + 0]) * sa[64 + c + 0]; x = x > 0.f ? x : 0.01f * x; r.x = x;
    x = (va.y - sa[c + 1]) * sa[64 + c + 1]; x = x > 0.f ? x : 0.01f * x; r.y = x;
    x = (va.z - sa[c + 2]) * sa[64 + c + 2]; x = x > 0.f ? x : 0.01f * x; r.z = x;
    x = (va.w - sa[c + 3]) * sa[64 + c + 3]; x = x > 0.f ? x : 0.01f * x; r.w = x;
    x = (vb.x - sb[c + 0]) * sb[64 + c + 0]; x = x > 0.f ? x : 0.01f * x; r.x += x;
    x = (vb.y - sb[c + 1]) * sb[64 + c + 1]; x = x > 0.f ? x : 0.01f * x; r.y += x;
    x = (vb.z - sb[c + 2]) * sb[64 + c + 2]; x = x > 0.f ? x : 0.01f * x; r.z += x;
    x = (vb.w - sb[c + 3]) * sb[64 + c + 3]; x = x > 0.f ? x : 0.01f * x; r.w += x;
    o[i] = r;
}

// out[m] = [x1 | x2 | x3] @ down_w  (fp32 FFMA2 path, warp-autonomous)
__global__ void __launch_bounds__(256)
final_kernel(const float* __restrict__ X1, const float* __restrict__ X2,
             const float* __restrict__ X3, const float* __restrict__ Wp,
             float* __restrict__ out, int M)
{
    __shared__ __align__(16) float buf[8][2][8][64];
    const int t = threadIdx.x;
    const int w = t >> 5;
    const int l = t & 31;
    const int rowBase = (blockIdx.x * 8 + w) * 8;
    const int gr = l >> 2;
    const int gp = l & 3;
    const int grow = rowBase + gr;
    const bool rowOK = (grow < M);

    const float* srcs[3] = {X1, X2, X3};
    auto prefetch = [&](int s, int b) {
        const float* src = srcs[s] + (size_t)(rowOK ? grow : 0) * 64;
        const int sz = rowOK ? 16 : 0;
        const uint32_t dbase = (uint32_t)__cvta_generic_to_shared(&buf[w][b][gr][0]);
#pragma unroll
        for (int i = 0; i < 4; ++i) {
            const int c4 = gp + 4 * i;
            asm volatile("cp.async.ca.shared.global [%0], [%1], 16, %2;\n"
                         :: "r"(dbase + c4 * 16), "l"(src + c4 * 4), "r"(sz));
        }
        asm volatile("cp.async.commit_group;\n");
    };

    u64 accA[8], accB[8];
#pragma unroll
    for (int r = 0; r < 8; ++r) { accA[r] = 0ull; accB[r] = 0ull; }

    prefetch(0, 0);
    for (int s = 0; s < 3; ++s) {
        if (s + 1 < 3) {
            prefetch(s + 1, (s + 1) & 1);
            asm volatile("cp.async.wait_group 1;\n");
        } else {
            asm volatile("cp.async.wait_group 0;\n");
        }
        __syncwarp();
        const float* wk = Wp + (size_t)s * (64 * 64);
        const float* frow = &buf[w][s & 1][0][0];
#pragma unroll
        for (int q = 0; q < 16; ++q) {
            const ulonglong2 wa = *reinterpret_cast<const ulonglong2*>(wk + (q * 64 + l) * 4);
            const ulonglong2 wb = *reinterpret_cast<const ulonglong2*>(wk + (q * 64 + l + 32) * 4);
#pragma unroll
            for (int r = 0; r < 8; ++r) {
                const ulonglong2 s2 =
                    *reinterpret_cast<const ulonglong2*>(frow + r * 64 + q * 4);
                accA[r] = ffma2(s2.x, wa.x, accA[r]);
                accA[r] = ffma2(s2.y, wa.y, accA[r]);
                accB[r] = ffma2(s2.x, wb.x, accB[r]);
                accB[r] = ffma2(s2.y, wb.y, accB[r]);
            }
        }
        __syncwarp();
    }
#pragma unroll
    for (int r = 0; r < 8; ++r) {
        const int orow = rowBase + r;
        if (orow < M) {
            out[(size_t)orow * 64 + l] =
                __uint_as_float((unsigned)accA[r]) + __uint_as_float((unsigned)(accA[r] >> 32));
            out[(size_t)orow * 64 + l + 32] =
                __uint_as_float((unsigned)accB[r]) + __uint_as_float((unsigned)(accB[r] >> 32));
        }
    }
}

// ---------------------------------------------------------------------------
extern "C" void kernel_launch(void* const* d_in, const int* in_sizes, int n_in,
                              void* d_out, int out_size)
{
    const float* feats  = (const float*)d_in[0];
    const float* down_w = (const float*)d_in[14];
    const int* n331_1 = (const int*)d_in[15];
    const int* n313_1 = (const int*)d_in[16];
    const int* pool_n = (const int*)d_in[17];
    const int* n331_2 = (const int*)d_in[18];
    const int* n313_2 = (const int*)d_in[19];
    const int* n331_3 = (const int*)d_in[20];
    const int* n313_3 = (const int*)d_in[21];

    const int N = in_sizes[0] / 32;
    const int M = out_size / 64;

    float *A, *B, *C, *X1, *X2, *X3, *pS, *pQ, *st, *Wt;
    uint32_t* Wb;
    cudaGetSymbolAddress((void**)&A,  g_A);
    cudaGetSymbolAddress((void**)&B,  g_B);
    cudaGetSymbolAddress((void**)&C,  g_C);
    cudaGetSymbolAddress((void**)&X1, g_X1);
    cudaGetSymbolAddress((void**)&X2, g_X2);
    cudaGetSymbolAddress((void**)&X3, g_X3);
    cudaGetSymbolAddress((void**)&pS, g_pS);
    cudaGetSymbolAddress((void**)&pQ, g_pQ);
    cudaGetSymbolAddress((void**)&st, g_st);
    cudaGetSymbolAddress((void**)&Wt, g_Wt);
    cudaGetSymbolAddress((void**)&Wb, g_Wb);
    float* st0 = st;
    float* st1 = st + 128;
    float* st2 = st + 256;
    float* st3 = st + 384;

    const size_t o0 = 0;
    const size_t o1 = 18432;
    const size_t o2 = 55296;
    const size_t o3 = 73728;
    const size_t o4 = 110592;
    const size_t o5 = 221184;
    const size_t o6 = 258048;
    const size_t o7 = 294912;
    const size_t o8 = 331776;
    const size_t o9 = 368640;
    const size_t o10 = 405504;
    const size_t o11 = 442368;
    const size_t o12 = 479232;

    // dynamic smem: A frag buffers (8 warps x 2 bufs x (hi+lo))
    const int SM2 = 8 * 2 * (2 * 2 * 4 * 33 * 4);   // KTILES=2: 33792
    const int SM4 = 8 * 2 * (2 * 4 * 4 * 33 * 4);   // KTILES=4: 67584
    cudaFuncSetAttribute(mma_conv<2, 9, true, false>,
                         cudaFuncAttributeMaxDynamicSharedMemorySize, SM2);
    cudaFuncSetAttribute(mma_conv<4, 9, true, false>,
                         cudaFuncAttributeMaxDynamicSharedMemorySize, SM4);
    cudaFuncSetAttribute(mma_conv<4, 9, true, true>,
                         cudaFuncAttributeMaxDynamicSharedMemorySize, SM4);
    cudaFuncSetAttribute(mma_conv<4, 27, false, false>,
                         cudaFuncAttributeMaxDynamicSharedMemorySize, SM4);

    WPtrs wp;
    for (int i = 0; i < 13; ++i) wp.p[i] = (const float*)d_in[1 + i];
    wprep<<<135, 256>>>(wp, Wb);
    wtrans_down<<<3, 256>>>(down_w, Wt);

    const int gN = (N + 127) / 128;
    const int gM = (M + 127) / 128;
    const long long n4N = (long long)N * 16;
    const long long n4M = (long long)M * 16;
    const int gbN = (int)((n4N + 255) / 256);
    const int gbM = (int)((n4M + 255) / 256);
    const int gMf = (M + 63) / 64;

    // ---- block 1 (N rows, 32 -> 64) ----
    mma_conv<2, 9, true, false><<<gN, 256, SM2>>>(feats, N, n331_1, N, Wb + o0, A, pS, pQ, st0, nullptr);
    mma_conv<4, 9, true, true ><<<gN, 256, SM4>>>(A,     N, n313_1, N, Wb + o1, B, pS, pQ, st1, st0);
    mma_conv<2, 9, true, false><<<gN, 256, SM2>>>(feats, N, n313_1, N, Wb + o2, C, pS, pQ, st2, nullptr);
    mma_conv<4, 9, true, true ><<<gN, 256, SM4>>>(C,     N, n331_1, N, Wb + o3, A, pS, pQ, st3, st2);
    combine_kernel<<<gbN, 256>>>((const float4*)A, st3, (const float4*)B, st1,
                                 (float4*)C, n4N);

    // ---- pool (K=27): C (N rows) -> X1 (M rows) ----
    mma_conv<4, 27, false, false><<<gM, 256, SM4>>>(C, N, pool_n, M, Wb + o4, X1,
                                                    nullptr, nullptr, nullptr, nullptr);

    // ---- block 2 (M rows, dilation 2) ----
    mma_conv<4, 9, true, false><<<gM, 256, SM4>>>(X1, M, n331_2, M, Wb + o5, A, pS, pQ, st0, nullptr);
    mma_conv<4, 9, true, true ><<<gM, 256, SM4>>>(A,  M, n313_2, M, Wb + o6, B, pS, pQ, st1, st0);
    mma_conv<4, 9, true, false><<<gM, 256, SM4>>>(X1, M, n313_2, M, Wb + o7, C, pS, pQ, st2, nullptr);
    mma_conv<4, 9, true, true ><<<gM, 256, SM4>>>(C,  M, n331_2, M, Wb + o8, A, pS, pQ, st3, st2);
    combine_kernel<<<gbM, 256>>>((const float4*)A, st3, (const float4*)B, st1,
                                 (float4*)X2, n4M);

    // ---- block 3 (M rows, dilation 3) ----
    mma_conv<4, 9, true, false><<<gM, 256, SM4>>>(X2, M, n331_3, M, Wb + o9,  A, pS, pQ, st0, nullptr);
    mma_conv<4, 9, true, true ><<<gM, 256, SM4>>>(A,  M, n313_3, M, Wb + o10, B, pS, pQ, st1, st0);
    mma_conv<4, 9, true, false><<<gM, 256, SM4>>>(X2, M, n313_3, M, Wb + o11, C, pS, pQ, st2, nullptr);
    mma_conv<4, 9, true, true ><<<gM, 256, SM4>>>(C,  M, n313_3 == n331_3 ? n331_3 : n331_3, M, Wb + o12, A, pS, pQ, st3, st2);
    combine_kernel<<<gbM, 256>>>((const float4*)A, st3, (const float4*)B, st1,
                                 (float4*)X3, n4M);

    // ---- final 1x1 fuse ----
    final_kernel<<<gMf, 256>>>(X1, X2, X3, Wt, (float*)d_out, M);
}

// round 12
// speedup vs baseline: 1.1247x; 1.1247x over previous
#include <cuda_runtime.h>
#include <cuda_bf16.h>
#include <cstdint>

typedef unsigned long long u64;

// ---------------------------------------------------------------------------
// dilate_block — round 12: R10 base + row-segment gather:
//   4 consecutive lanes read 4 consecutive float4 of one row
//   -> 8 lines per LDG.128 instead of 32 (gather wavefronts /4),
//   no shuffles, no extra instructions, registers unchanged.
// ---------------------------------------------------------------------------

static constexpr int MAXR = 640000;
static constexpr int MAXBLK = MAXR / 128 + 2;

__device__ __align__(16) float g_A [MAXR * 64];
__device__ __align__(16) float g_B [MAXR * 64];
__device__ __align__(16) float g_C [MAXR * 64];
__device__ __align__(16) float g_X1[MAXR * 64];
__device__ __align__(16) float g_X2[MAXR * 64];
__device__ __align__(16) float g_X3[MAXR * 64];
__device__ float g_pS[MAXBLK * 64];
__device__ float g_pQ[MAXBLK * 64];
__device__ float g_st[4 * 128];
__device__ unsigned g_tick;                             // zero-init, self-resetting
__device__ __align__(16) float g_Wt[3 * 4096];          // down_w packed (fp32 path)
__device__ __align__(16) uint32_t g_Wb[516096];         // conv weights, frag-major, hi/lo interleaved

// ---------------- helpers ----------------
__device__ __forceinline__ uint32_t smem_u32(const void* p) {
    uint32_t a;
    asm("{ .reg .u64 t; cvta.to.shared.u64 t, %1; cvt.u32.u64 %0, t; }" : "=r"(a) : "l"(p));
    return a;
}
__device__ __forceinline__ uint32_t cvt2(float lo, float hi) {
    uint32_t r;
    asm("cvt.rn.bf16x2.f32 %0, %1, %2;" : "=r"(r) : "f"(hi), "f"(lo));
    return r;
}
__device__ __forceinline__ uint32_t lds32(uint32_t a) {
    uint32_t v;
    asm volatile("ld.shared.b32 %0, [%1];" : "=r"(v) : "r"(a));
    return v;
}
__device__ __forceinline__ void st32(uint32_t a, uint32_t v) {
    asm volatile("st.shared.b32 [%0], %1;" :: "r"(a), "r"(v));
}
__device__ __forceinline__ void mma_bf16(float d[4], const uint32_t a[4], const uint32_t b[2]) {
    asm volatile(
        "mma.sync.aligned.m16n8k16.row.col.f32.bf16.bf16.f32 "
        "{%0,%1,%2,%3}, {%4,%5,%6,%7}, {%8,%9}, {%0,%1,%2,%3};"
        : "+f"(d[0]), "+f"(d[1]), "+f"(d[2]), "+f"(d[3])
        : "r"(a[0]), "r"(a[1]), "r"(a[2]), "r"(a[3]), "r"(b[0]), "r"(b[1]));
}
__device__ __forceinline__ u64 ffma2(u64 a, u64 b, u64 c) {
    u64 d;
    asm("fma.rn.f32x2 %0, %1, %2, %3;" : "=l"(d) : "l"(a), "l"(b), "l"(c));
    return d;
}

// ---------------------------------------------------------------------------
// weight prep: fp32 [K][CIN][64] -> per tap [kt][nt(8)][lane(32)][hi0,hi1,lo0,lo1]
// ---------------------------------------------------------------------------
struct WPtrs { const float* p[13]; };

__global__ void __launch_bounds__(256)
wprep(WPtrs w, uint32_t* __restrict__ dst)
{
    const int nT[13]   = {9,9,9,9,27,9,9,9,9,9,9,9,9};
    const int cinA[13] = {32,64,32,64,64,64,64,64,64,64,64,64,64};
    const int offW[13] = {0,18432,55296,73728,110592,221184,258048,294912,
                          331776,368640,405504,442368,479232};
    int b = blockIdx.x, c = 0;
    while (b >= nT[c]) { b -= nT[c]; ++c; }
    const int CIN = cinA[c];
    const int KT = CIN / 16;
    const float* src = w.p[c] + (size_t)b * CIN * 64;
    uint16_t* tap = reinterpret_cast<uint16_t*>(dst + offW[c] + (size_t)b * (KT * 1024));
    for (int e = threadIdx.x; e < CIN * 64; e += 256) {
        const int ci = e >> 6, co = e & 63;
        const float x = src[e];
        __nv_bfloat16 hb = __float2bfloat16(x);
        __nv_bfloat16 lb = __float2bfloat16(x - __bfloat162float(hb));
        const int kt = ci >> 4, ck = (ci & 15) >> 1, j = ci & 1;
        const int regb = (ck >= 4) ? 1 : 0;
        const int tt = ck & 3, nt = co >> 3, gg = co & 7;
        const int word = (((kt * 8 + nt) * 32 + (gg * 4 + tt)) * 4) + regb;  // hi at +0/+1
        tap[word * 2 + j]       = *reinterpret_cast<unsigned short*>(&hb);
        tap[(word + 2) * 2 + j] = *reinterpret_cast<unsigned short*>(&lb);   // lo at +2/+3
    }
}

__global__ void wtrans_down(const float* __restrict__ src, float* __restrict__ dst)
{
    const int k = blockIdx.x;
    for (int e = threadIdx.x; e < 4096; e += 256) {
        const int ci = e >> 6, co = e & 63;
        dst[k * 4096 + ((ci >> 2) * 64 + co) * 4 + (ci & 3)] = src[k * 4096 + e];
    }
}

// ---------------------------------------------------------------------------
// mma.sync gather-GEMM conv. 256 thr, 8 warps x 16 rows = 128 rows per block.
// Row-segment gather; fused input BN (BN) and output BN stats (STATS).
// ---------------------------------------------------------------------------
template <int KTILES, int KTAPS, bool STATS, bool BN>
__global__ void __launch_bounds__(256, 2)
mma_conv(const float* __restrict__ in, int nIn,
         const int* __restrict__ nbr, int nOut,
         const uint32_t* __restrict__ Wg,
         float* __restrict__ out,
         float* __restrict__ pSum, float* __restrict__ pSq,
         float* __restrict__ stOut, const float* __restrict__ bnIn)
{
    constexpr int CIN = KTILES * 16;
    constexpr int TAPW = KTILES * 1024;              // b32 words per tap
    constexpr int ATERM_BYTES = KTILES * 4 * 33 * 4; // stride-33 padded frag layout
    constexpr int ABUF_BYTES = 2 * ATERM_BYTES;
    constexpr int IPP = CIN / 16;                    // float4 loads per lane per phase
    constexpr int NF4 = 2 * IPP;                     // total per lane (2 phases)

    extern __shared__ __align__(16) char smem[];
    __shared__ float redS[8][64];
    __shared__ float redQ[8][64];
    __shared__ float s_st[128];
    __shared__ unsigned s_last;

    const uint32_t abase = smem_u32(smem);
    const int t = threadIdx.x;
    const int w = t >> 5;
    const int l = t & 31;
    const int rowBase = blockIdx.x * 128 + w * 16;

    if (BN) {
        if (t < 128) s_st[t] = bnIn[t];
        __syncthreads();
    }

    const uint32_t abuf0 = abase + (uint32_t)(w * 2 + 0) * ABUF_BYTES;
    const uint32_t abuf1 = abase + (uint32_t)(w * 2 + 1) * ABUF_BYTES;

    // row-segment gather: phase p covers rows p*8..p*8+7; lanes 4r..4r+3 own
    // row r; lane reads float4 index (l&3)+4i  (64B contiguous per 4 lanes).
    float4 pf[NF4];
    auto prefetch = [&](int k) {
#pragma unroll
        for (int p = 0; p < 2; ++p) {
            const int row = p * 8 + (l >> 2);
            const int grow = rowBase + row;
            const int j = (grow < nOut) ? __ldg(&nbr[(size_t)k * nOut + grow]) : nIn;
            const bool v = (j < nIn);
            const float* base = in + (size_t)(v ? j : 0) * CIN;
#pragma unroll
            for (int i = 0; i < IPP; ++i) {
                const int c4 = ((l & 3) + 4 * i) * 4;
                float4 vv = make_float4(0.f, 0.f, 0.f, 0.f);
                if (v) {
                    vv = *reinterpret_cast<const float4*>(base + c4);
                    if (BN) {
                        vv.x = (vv.x - s_st[c4 + 0]) * s_st[64 + c4 + 0];
                        vv.y = (vv.y - s_st[c4 + 1]) * s_st[64 + c4 + 1];
                        vv.z = (vv.z - s_st[c4 + 2]) * s_st[64 + c4 + 2];
                        vv.w = (vv.w - s_st[c4 + 3]) * s_st[64 + c4 + 3];
                        vv.x = vv.x > 0.f ? vv.x : 0.01f * vv.x;
                        vv.y = vv.y > 0.f ? vv.y : 0.01f * vv.y;
                        vv.z = vv.z > 0.f ? vv.z : 0.01f * vv.z;
                        vv.w = vv.w > 0.f ? vv.w : 0.01f * vv.w;
                    }
                }
                pf[p * IPP + i] = vv;
            }
        }
    };
    auto convert_sts = [&](uint32_t buf) {
#pragma unroll
        for (int p = 0; p < 2; ++p) {
            const int row = p * 8 + (l >> 2);
#pragma unroll
            for (int i = 0; i < IPP; ++i) {
                const int c = ((l & 3) + 4 * i) * 4;
                const int kt = c >> 4;
                const int q = c & 15;                    // 0,4,8,12
                const int regb = (row >> 3) | ((q & 8) ? 2 : 0);
                const int lane0 = ((row & 7) << 2) + ((q & 4) ? 2 : 0);
                const uint32_t w0 = (uint32_t)(((kt * 4 + regb) * 33 + lane0) * 4);
                const float4 x = pf[p * IPP + i];
                const uint32_t h0 = cvt2(x.x, x.y);
                const uint32_t h1 = cvt2(x.z, x.w);
                const float l0 = x.x - __uint_as_float(h0 << 16);
                const float l1 = x.y - __uint_as_float(h0 & 0xFFFF0000u);
                const float l2 = x.z - __uint_as_float(h1 << 16);
                const float l3 = x.w - __uint_as_float(h1 & 0xFFFF0000u);
                const uint32_t q0 = cvt2(l0, l1);
                const uint32_t q1 = cvt2(l2, l3);
                st32(buf + w0, h0);
                st32(buf + w0 + 4, h1);
                st32(buf + ATERM_BYTES + w0, q0);
                st32(buf + ATERM_BYTES + w0 + 4, q1);
            }
        }
    };

    float acc[8][4];
#pragma unroll
    for (int nt = 0; nt < 8; ++nt)
#pragma unroll
        for (int j = 0; j < 4; ++j) acc[nt][j] = 0.f;

    prefetch(0);
    convert_sts(abuf0);
    __syncwarp();

    for (int k = 0; k < KTAPS; ++k) {
        const uint32_t cur = (k & 1) ? abuf1 : abuf0;
        const uint32_t nxt = (k & 1) ? abuf0 : abuf1;
        if (k + 1 < KTAPS) prefetch(k + 1);
        const uint32_t* wtap = Wg + (size_t)k * TAPW;
#pragma unroll
        for (int kt = 0; kt < KTILES; ++kt) {
            uint32_t ah[4], al[4];
#pragma unroll
            for (int j = 0; j < 4; ++j) {
                const uint32_t ao = (uint32_t)(((kt * 4 + j) * 33 + l) * 4);
                ah[j] = lds32(cur + ao);
                al[j] = lds32(cur + ATERM_BYTES + ao);
            }
#pragma unroll
            for (int nt = 0; nt < 8; ++nt) {
                const uint32_t widx = ((kt * 8 + nt) * 32 + l) * 4;
                const uint4 bv = __ldg(reinterpret_cast<const uint4*>(wtap + widx));
                uint32_t bh[2] = {bv.x, bv.y};
                uint32_t bl[2] = {bv.z, bv.w};
                mma_bf16(acc[nt], ah, bh);
                mma_bf16(acc[nt], al, bh);
                mma_bf16(acc[nt], ah, bl);
            }
        }
        if (k + 1 < KTAPS) convert_sts(nxt);
        __syncwarp();
    }

    // ---- epilogue: write D fragments ----
    const int dg = l >> 2, dt = l & 3;
    const int row0 = rowBase + dg;
    const int row1 = row0 + 8;
    if (row0 < nOut) {
        float* o = out + (size_t)row0 * 64 + dt * 2;
#pragma unroll
        for (int nt = 0; nt < 8; ++nt)
            *reinterpret_cast<float2*>(o + nt * 8) = make_float2(acc[nt][0], acc[nt][1]);
    }
    if (row1 < nOut) {
        float* o = out + (size_t)row1 * 64 + dt * 2;
#pragma unroll
        for (int nt = 0; nt < 8; ++nt)
            *reinterpret_cast<float2*>(o + nt * 8) = make_float2(acc[nt][2], acc[nt][3]);
    }

    if (STATS) {
#pragma unroll
        for (int nt = 0; nt < 8; ++nt) {
#pragma unroll
            for (int j = 0; j < 2; ++j) {
                float ss = acc[nt][j] + acc[nt][j + 2];
                float qq = acc[nt][j] * acc[nt][j] + acc[nt][j + 2] * acc[nt][j + 2];
                ss += __shfl_xor_sync(0xFFFFFFFFu, ss, 4);
                qq += __shfl_xor_sync(0xFFFFFFFFu, qq, 4);
                ss += __shfl_xor_sync(0xFFFFFFFFu, ss, 8);
                qq += __shfl_xor_sync(0xFFFFFFFFu, qq, 8);
                ss += __shfl_xor_sync(0xFFFFFFFFu, ss, 16);
                qq += __shfl_xor_sync(0xFFFFFFFFu, qq, 16);
                if (l < 4) {
                    redS[w][nt * 8 + l * 2 + j] = ss;
                    redQ[w][nt * 8 + l * 2 + j] = qq;
                }
            }
        }
        __syncthreads();
        if (t < 64) {
            float s = 0.f, q = 0.f;
#pragma unroll
            for (int ww = 0; ww < 8; ++ww) { s += redS[ww][t]; q += redQ[ww][t]; }
            pSum[(size_t)blockIdx.x * 64 + t] = s;
            pSq [(size_t)blockIdx.x * 64 + t] = q;
        }
        __syncthreads();
        __threadfence();
        if (t == 0) s_last = (atomicAdd(&g_tick, 1u) == gridDim.x - 1u) ? 1u : 0u;
        __syncthreads();
        if (s_last) {
            __threadfence();
            const int co = t & 63, sub = t >> 6;
            float s = 0.f, q = 0.f;
            for (int b = sub; b < (int)gridDim.x; b += 4) {
                s += pSum[(size_t)b * 64 + co];
                q += pSq[(size_t)b * 64 + co];
            }
            redS[sub][co] = s;
            redQ[sub][co] = q;
            __syncthreads();
            if (t < 64) {
                const float S = (redS[0][t] + redS[1][t]) + (redS[2][t] + redS[3][t]);
                const float Q = (redQ[0][t] + redQ[1][t]) + (redQ[2][t] + redQ[3][t]);
                const float inv = 1.0f / (float)nOut;
                const float m = S * inv;
                const float var = Q * inv - m * m;
                stOut[t] = m;
                stOut[64 + t] = rsqrtf(var + 1e-5f);
            }
            __syncthreads();
            if (t == 0) g_tick = 0u;
        }
    }
}

// ---------------------------------------------------------------------------
__global__ void combine_kernel(const float4* __restrict__ a, const float* __restrict__ sa,
                               const float4* __restrict__ b, const float* __restrict__ sb,
                               float4* __restrict__ o, long long n4)
{
    const long long i = (long long)blockIdx.x * blockDim.x + threadIdx.x;
    if (i >= n4) return;
    const int c = ((int)(i & 15)) * 4;
    float4 va = a[i];
    float4 vb = b[i];
    float4 r;
    float x;
    x = (va.x - sa[c + 0]) * sa[64 + c + 0]; x = x > 0.f ? x : 0.01f * x; r.x = x;
    x = (va.y - sa[c + 1]) * sa[64 + c + 1]; x = x > 0.f ? x : 0.01f * x; r.y = x;
    x = (va.z - sa[c + 2]) * sa[64 + c + 2]; x = x > 0.f ? x : 0.01f * x; r.z = x;
    x = (va.w - sa[c + 3]) * sa[64 + c + 3]; x = x > 0.f ? x : 0.01f * x; r.w = x;
    x = (vb.x - sb[c + 0]) * sb[64 + c + 0]; x = x > 0.f ? x : 0.01f * x; r.x += x;
    x = (vb.y - sb[c + 1]) * sb[64 + c + 1]; x = x > 0.f ? x : 0.01f * x; r.y += x;
    x = (vb.z - sb[c + 2]) * sb[64 + c + 2]; x = x > 0.f ? x : 0.01f * x; r.z += x;
    x = (vb.w - sb[c + 3]) * sb[64 + c + 3]; x = x > 0.f ? x : 0.01f * x; r.w += x;
    o[i] = r;
}

// out[m] = [x1 | x2 | x3] @ down_w  (fp32 FFMA2 path, warp-autonomous)
__global__ void __launch_bounds__(256)
final_kernel(const float* __restrict__ X1, const float* __restrict__ X2,
             const float* __restrict__ X3, const float* __restrict__ Wp,
             float* __restrict__ out, int M)
{
    __shared__ __align__(16) float buf[8][2][8][64];
    const int t = threadIdx.x;
    const int w = t >> 5;
    const int l = t & 31;
    const int rowBase = (blockIdx.x * 8 + w) * 8;
    const int gr = l >> 2;
    const int gp = l & 3;
    const int grow = rowBase + gr;
    const bool rowOK = (grow < M);

    const float* srcs[3] = {X1, X2, X3};
    auto prefetch = [&](int s, int b) {
        const float* src = srcs[s] + (size_t)(rowOK ? grow : 0) * 64;
        const int sz = rowOK ? 16 : 0;
        const uint32_t dbase = (uint32_t)__cvta_generic_to_shared(&buf[w][b][gr][0]);
#pragma unroll
        for (int i = 0; i < 4; ++i) {
            const int c4 = gp + 4 * i;
            asm volatile("cp.async.ca.shared.global [%0], [%1], 16, %2;\n"
                         :: "r"(dbase + c4 * 16), "l"(src + c4 * 4), "r"(sz));
        }
        asm volatile("cp.async.commit_group;\n");
    };

    u64 accA[8], accB[8];
#pragma unroll
    for (int r = 0; r < 8; ++r) { accA[r] = 0ull; accB[r] = 0ull; }

    prefetch(0, 0);
    for (int s = 0; s < 3; ++s) {
        if (s + 1 < 3) {
            prefetch(s + 1, (s + 1) & 1);
            asm volatile("cp.async.wait_group 1;\n");
        } else {
            asm volatile("cp.async.wait_group 0;\n");
        }
        __syncwarp();
        const float* wk = Wp + (size_t)s * (64 * 64);
        const float* frow = &buf[w][s & 1][0][0];
#pragma unroll
        for (int q = 0; q < 16; ++q) {
            const ulonglong2 wa = *reinterpret_cast<const ulonglong2*>(wk + (q * 64 + l) * 4);
            const ulonglong2 wb = *reinterpret_cast<const ulonglong2*>(wk + (q * 64 + l + 32) * 4);
#pragma unroll
            for (int r = 0; r < 8; ++r) {
                const ulonglong2 s2 =
                    *reinterpret_cast<const ulonglong2*>(frow + r * 64 + q * 4);
                accA[r] = ffma2(s2.x, wa.x, accA[r]);
                accA[r] = ffma2(s2.y, wa.y, accA[r]);
                accB[r] = ffma2(s2.x, wb.x, accB[r]);
                accB[r] = ffma2(s2.y, wb.y, accB[r]);
            }
        }
        __syncwarp();
    }
#pragma unroll
    for (int r = 0; r < 8; ++r) {
        const int orow = rowBase + r;
        if (orow < M) {
            out[(size_t)orow * 64 + l] =
                __uint_as_float((unsigned)accA[r]) + __uint_as_float((unsigned)(accA[r] >> 32));
            out[(size_t)orow * 64 + l + 32] =
                __uint_as_float((unsigned)accB[r]) + __uint_as_float((unsigned)(accB[r] >> 32));
        }
    }
}

// ---------------------------------------------------------------------------
extern "C" void kernel_launch(void* const* d_in, const int* in_sizes, int n_in,
                              void* d_out, int out_size)
{
    const float* feats  = (const float*)d_in[0];
    const float* down_w = (const float*)d_in[14];
    const int* n331_1 = (const int*)d_in[15];
    const int* n313_1 = (const int*)d_in[16];
    const int* pool_n = (const int*)d_in[17];
    const int* n331_2 = (const int*)d_in[18];
    const int* n313_2 = (const int*)d_in[19];
    const int* n331_3 = (const int*)d_in[20];
    const int* n313_3 = (const int*)d_in[21];

    const int N = in_sizes[0] / 32;
    const int M = out_size / 64;

    float *A, *B, *C, *X1, *X2, *X3, *pS, *pQ, *st, *Wt;
    uint32_t* Wb;
    cudaGetSymbolAddress((void**)&A,  g_A);
    cudaGetSymbolAddress((void**)&B,  g_B);
    cudaGetSymbolAddress((void**)&C,  g_C);
    cudaGetSymbolAddress((void**)&X1, g_X1);
    cudaGetSymbolAddress((void**)&X2, g_X2);
    cudaGetSymbolAddress((void**)&X3, g_X3);
    cudaGetSymbolAddress((void**)&pS, g_pS);
    cudaGetSymbolAddress((void**)&pQ, g_pQ);
    cudaGetSymbolAddress((void**)&st, g_st);
    cudaGetSymbolAddress((void**)&Wt, g_Wt);
    cudaGetSymbolAddress((void**)&Wb, g_Wb);
    float* st0 = st;
    float* st1 = st + 128;
    float* st2 = st + 256;
    float* st3 = st + 384;

    const size_t o0 = 0;
    const size_t o1 = 18432;
    const size_t o2 = 55296;
    const size_t o3 = 73728;
    const size_t o4 = 110592;
    const size_t o5 = 221184;
    const size_t o6 = 258048;
    const size_t o7 = 294912;
    const size_t o8 = 331776;
    const size_t o9 = 368640;
    const size_t o10 = 405504;
    const size_t o11 = 442368;
    const size_t o12 = 479232;

    // dynamic smem: A frag buffers (8 warps x 2 bufs x (hi+lo))
    const int SM2 = 8 * 2 * (2 * 2 * 4 * 33 * 4);   // KTILES=2: 33792
    const int SM4 = 8 * 2 * (2 * 4 * 4 * 33 * 4);   // KTILES=4: 67584
    cudaFuncSetAttribute(mma_conv<2, 9, true, false>,
                         cudaFuncAttributeMaxDynamicSharedMemorySize, SM2);
    cudaFuncSetAttribute(mma_conv<4, 9, true, false>,
                         cudaFuncAttributeMaxDynamicSharedMemorySize, SM4);
    cudaFuncSetAttribute(mma_conv<4, 9, true, true>,
                         cudaFuncAttributeMaxDynamicSharedMemorySize, SM4);
    cudaFuncSetAttribute(mma_conv<4, 27, false, false>,
                         cudaFuncAttributeMaxDynamicSharedMemorySize, SM4);

    WPtrs wp;
    for (int i = 0; i < 13; ++i) wp.p[i] = (const float*)d_in[1 + i];
    wprep<<<135, 256>>>(wp, Wb);
    wtrans_down<<<3, 256>>>(down_w, Wt);

    const int gN = (N + 127) / 128;
    const int gM = (M + 127) / 128;
    const long long n4N = (long long)N * 16;
    const long long n4M = (long long)M * 16;
    const int gbN = (int)((n4N + 255) / 256);
    const int gbM = (int)((n4M + 255) / 256);
    const int gMf = (M + 63) / 64;

    // ---- block 1 (N rows, 32 -> 64) ----
    mma_conv<2, 9, true, false><<<gN, 256, SM2>>>(feats, N, n331_1, N, Wb + o0, A, pS, pQ, st0, nullptr);
    mma_conv<4, 9, true, true ><<<gN, 256, SM4>>>(A,     N, n313_1, N, Wb + o1, B, pS, pQ, st1, st0);
    mma_conv<2, 9, true, false><<<gN, 256, SM2>>>(feats, N, n313_1, N, Wb + o2, C, pS, pQ, st2, nullptr);
    mma_conv<4, 9, true, true ><<<gN, 256, SM4>>>(C,     N, n331_1, N, Wb + o3, A, pS, pQ, st3, st2);
    combine_kernel<<<gbN, 256>>>((const float4*)A, st3, (const float4*)B, st1,
                                 (float4*)C, n4N);

    // ---- pool (K=27): C (N rows) -> X1 (M rows) ----
    mma_conv<4, 27, false, false><<<gM, 256, SM4>>>(C, N, pool_n, M, Wb + o4, X1,
                                                    nullptr, nullptr, nullptr, nullptr);

    // ---- block 2 (M rows, dilation 2) ----
    mma_conv<4, 9, true, false><<<gM, 256, SM4>>>(X1, M, n331_2, M, Wb + o5, A, pS, pQ, st0, nullptr);
    mma_conv<4, 9, true, true ><<<gM, 256, SM4>>>(A,  M, n313_2, M, Wb + o6, B, pS, pQ, st1, st0);
    mma_conv<4, 9, true, false><<<gM, 256, SM4>>>(X1, M, n313_2, M, Wb + o7, C, pS, pQ, st2, nullptr);
    mma_conv<4, 9, true, true ><<<gM, 256, SM4>>>(C,  M, n331_2, M, Wb + o8, A, pS, pQ, st3, st2);
    combine_kernel<<<gbM, 256>>>((const float4*)A, st3, (const float4*)B, st1,
                                 (float4*)X2, n4M);

    // ---- block 3 (M rows, dilation 3) ----
    mma_conv<4, 9, true, false><<<gM, 256, SM4>>>(X2, M, n331_3, M, Wb + o9,  A, pS, pQ, st0, nullptr);
    mma_conv<4, 9, true, true ><<<gM, 256, SM4>>>(A,  M, n313_3, M, Wb + o10, B, pS, pQ, st1, st0);
    mma_conv<4, 9, true, false><<<gM, 256, SM4>>>(X2, M, n313_3, M, Wb + o11, C, pS, pQ, st2, nullptr);
    mma_conv<4, 9, true, true ><<<gM, 256, SM4>>>(C,  M, n331_3, M, Wb + o12, A, pS, pQ, st3, st2);
    combine_kernel<<<gbM, 256>>>((const float4*)A, st3, (const float4*)B, st1,
                                 (float4*)X3, n4M);

    // ---- final 1x1 fuse ----
    final_kernel<<<gMf, 256>>>(X1, X2, X3, Wt, (float*)d_out, M);
}

// round 13
// speedup vs baseline: 1.2192x; 1.0840x over previous
#include <cuda_runtime.h>
#include <cuda_bf16.h>
#include <cstdint>

typedef unsigned long long u64;

// ---------------------------------------------------------------------------
// dilate_block — round 13: R10 conv body + dual-conv launches:
//   independent conv pairs (w1-chain / w2-chain) fused into one grid,
//   blockIdx splits into two halves -> 2x warps resident, latency hidden.
// ---------------------------------------------------------------------------

static constexpr int MAXR = 640000;
static constexpr int MAXBLK = MAXR / 128 + 2;

__device__ __align__(16) float g_A [MAXR * 64];
__device__ __align__(16) float g_B [MAXR * 64];
__device__ __align__(16) float g_C [MAXR * 64];
__device__ __align__(16) float g_D [MAXR * 64];
__device__ __align__(16) float g_X1[MAXR * 64];
__device__ __align__(16) float g_X2[MAXR * 64];
__device__ __align__(16) float g_X3[MAXR * 64];
__device__ float g_pS[2 * MAXBLK * 64];
__device__ float g_pQ[2 * MAXBLK * 64];
__device__ float g_st[4 * 128];
__device__ unsigned g_tick[2];                          // zero-init, self-resetting
__device__ __align__(16) float g_Wt[3 * 4096];          // down_w packed (fp32 path)
__device__ __align__(16) uint32_t g_Wb[516096];         // conv weights, frag-major, hi/lo interleaved

// ---------------- helpers ----------------
__device__ __forceinline__ uint32_t smem_u32(const void* p) {
    uint32_t a;
    asm("{ .reg .u64 t; cvta.to.shared.u64 t, %1; cvt.u32.u64 %0, t; }" : "=r"(a) : "l"(p));
    return a;
}
__device__ __forceinline__ uint32_t cvt2(float lo, float hi) {
    uint32_t r;
    asm("cvt.rn.bf16x2.f32 %0, %1, %2;" : "=r"(r) : "f"(hi), "f"(lo));
    return r;
}
__device__ __forceinline__ uint32_t lds32(uint32_t a) {
    uint32_t v;
    asm volatile("ld.shared.b32 %0, [%1];" : "=r"(v) : "r"(a));
    return v;
}
__device__ __forceinline__ void st32(uint32_t a, uint32_t v) {
    asm volatile("st.shared.b32 [%0], %1;" :: "r"(a), "r"(v));
}
__device__ __forceinline__ void mma_bf16(float d[4], const uint32_t a[4], const uint32_t b[2]) {
    asm volatile(
        "mma.sync.aligned.m16n8k16.row.col.f32.bf16.bf16.f32 "
        "{%0,%1,%2,%3}, {%4,%5,%6,%7}, {%8,%9}, {%0,%1,%2,%3};"
        : "+f"(d[0]), "+f"(d[1]), "+f"(d[2]), "+f"(d[3])
        : "r"(a[0]), "r"(a[1]), "r"(a[2]), "r"(a[3]), "r"(b[0]), "r"(b[1]));
}
__device__ __forceinline__ u64 ffma2(u64 a, u64 b, u64 c) {
    u64 d;
    asm("fma.rn.f32x2 %0, %1, %2, %3;" : "=l"(d) : "l"(a), "l"(b), "l"(c));
    return d;
}

// ---------------------------------------------------------------------------
// weight prep: fp32 [K][CIN][64] -> per tap [kt][nt(8)][lane(32)][hi0,hi1,lo0,lo1]
// ---------------------------------------------------------------------------
struct WPtrs { const float* p[13]; };

__global__ void __launch_bounds__(256)
wprep(WPtrs w, uint32_t* __restrict__ dst)
{
    const int nT[13]   = {9,9,9,9,27,9,9,9,9,9,9,9,9};
    const int cinA[13] = {32,64,32,64,64,64,64,64,64,64,64,64,64};
    const int offW[13] = {0,18432,55296,73728,110592,221184,258048,294912,
                          331776,368640,405504,442368,479232};
    int b = blockIdx.x, c = 0;
    while (b >= nT[c]) { b -= nT[c]; ++c; }
    const int CIN = cinA[c];
    const int KT = CIN / 16;
    const float* src = w.p[c] + (size_t)b * CIN * 64;
    uint16_t* tap = reinterpret_cast<uint16_t*>(dst + offW[c] + (size_t)b * (KT * 1024));
    for (int e = threadIdx.x; e < CIN * 64; e += 256) {
        const int ci = e >> 6, co = e & 63;
        const float x = src[e];
        __nv_bfloat16 hb = __float2bfloat16(x);
        __nv_bfloat16 lb = __float2bfloat16(x - __bfloat162float(hb));
        const int kt = ci >> 4, ck = (ci & 15) >> 1, j = ci & 1;
        const int regb = (ck >= 4) ? 1 : 0;
        const int tt = ck & 3, nt = co >> 3, gg = co & 7;
        const int word = (((kt * 8 + nt) * 32 + (gg * 4 + tt)) * 4) + regb;  // hi at +0/+1
        tap[word * 2 + j]       = *reinterpret_cast<unsigned short*>(&hb);
        tap[(word + 2) * 2 + j] = *reinterpret_cast<unsigned short*>(&lb);   // lo at +2/+3
    }
}

__global__ void wtrans_down(const float* __restrict__ src, float* __restrict__ dst)
{
    const int k = blockIdx.x;
    for (int e = threadIdx.x; e < 4096; e += 256) {
        const int ci = e >> 6, co = e & 63;
        dst[k * 4096 + ((ci >> 2) * 64 + co) * 4 + (ci & 3)] = src[k * 4096 + e];
    }
}

// ---------------------------------------------------------------------------
// conv body (R10, proven): one 128-row tile per "virtual block" bid.
// ---------------------------------------------------------------------------
struct ConvArgs {
    const float* in;
    const int* nbr;
    const uint32_t* W;
    float* out;
    float* pS;
    float* pQ;
    float* st;
    const float* bn;
};

template <int KTILES, int KTAPS, bool STATS, bool BN>
__device__ __forceinline__ void conv_body(
    const ConvArgs a, int nIn, int nOut,
    unsigned* tick, int bid, int nBlocks, char* smem)
{
    constexpr int CIN = KTILES * 16;
    constexpr int TAPW = KTILES * 1024;
    constexpr int ATERM_BYTES = KTILES * 4 * 33 * 4;
    constexpr int ABUF_BYTES = 2 * ATERM_BYTES;
    constexpr int NF4 = CIN / 8;

    __shared__ float redS[8][64];
    __shared__ float redQ[8][64];
    __shared__ float s_st[128];
    __shared__ unsigned s_last;

    const uint32_t abase = smem_u32(smem);
    const int t = threadIdx.x;
    const int w = t >> 5;
    const int l = t & 31;
    const int rowBase = bid * 128 + w * 16;

    if (BN) {
        if (t < 128) s_st[t] = a.bn[t];
        __syncthreads();
    }

    const uint32_t abuf0 = abase + (uint32_t)(w * 2 + 0) * ABUF_BYTES;
    const uint32_t abuf1 = abase + (uint32_t)(w * 2 + 1) * ABUF_BYTES;

    const int gr = l >> 1;
    const int part = l & 1;
    const int grow = rowBase + gr;
    const bool rowOK = (grow < nOut);

    float4 pf[NF4];
    auto prefetch = [&](int k) {
        const int j = rowOK ? __ldg(&a.nbr[(size_t)k * nOut + grow]) : nIn;
        if (j < nIn) {
            const float4* s = reinterpret_cast<const float4*>(a.in + (size_t)j * CIN) + part * NF4;
#pragma unroll
            for (int i = 0; i < NF4; ++i) {
                float4 v = s[i];
                if (BN) {
                    const int c4 = (part * NF4 + i) * 4;
                    v.x = (v.x - s_st[c4 + 0]) * s_st[64 + c4 + 0];
                    v.y = (v.y - s_st[c4 + 1]) * s_st[64 + c4 + 1];
                    v.z = (v.z - s_st[c4 + 2]) * s_st[64 + c4 + 2];
                    v.w = (v.w - s_st[c4 + 3]) * s_st[64 + c4 + 3];
                    v.x = v.x > 0.f ? v.x : 0.01f * v.x;
                    v.y = v.y > 0.f ? v.y : 0.01f * v.y;
                    v.z = v.z > 0.f ? v.z : 0.01f * v.z;
                    v.w = v.w > 0.f ? v.w : 0.01f * v.w;
                }
                pf[i] = v;
            }
        } else {
#pragma unroll
            for (int i = 0; i < NF4; ++i) pf[i] = make_float4(0.f, 0.f, 0.f, 0.f);
        }
    };
    auto convert_sts = [&](uint32_t buf) {
#pragma unroll
        for (int i = 0; i < NF4; ++i) {
            const int kt = (KTILES == 4) ? (part * 2 + (i >> 2)) : part;
            const int regb = ((gr >> 3) & 1) | ((i & 2) ? 2 : 0);
            const int lane0 = ((gr & 7) << 2) + ((i & 1) << 1);
            const uint32_t w0 = (uint32_t)(((kt * 4 + regb) * 33 + lane0) * 4);
            const float4 x = pf[i];
            const uint32_t h0 = cvt2(x.x, x.y);
            const uint32_t h1 = cvt2(x.z, x.w);
            const float l0 = x.x - __uint_as_float(h0 << 16);
            const float l1 = x.y - __uint_as_float(h0 & 0xFFFF0000u);
            const float l2 = x.z - __uint_as_float(h1 << 16);
            const float l3 = x.w - __uint_as_float(h1 & 0xFFFF0000u);
            const uint32_t q0 = cvt2(l0, l1);
            const uint32_t q1 = cvt2(l2, l3);
            st32(buf + w0, h0);
            st32(buf + w0 + 4, h1);
            st32(buf + ATERM_BYTES + w0, q0);
            st32(buf + ATERM_BYTES + w0 + 4, q1);
        }
    };

    float acc[8][4];
#pragma unroll
    for (int nt = 0; nt < 8; ++nt)
#pragma unroll
        for (int j = 0; j < 4; ++j) acc[nt][j] = 0.f;

    prefetch(0);
    convert_sts(abuf0);
    __syncwarp();

    for (int k = 0; k < KTAPS; ++k) {
        const uint32_t cur = (k & 1) ? abuf1 : abuf0;
        const uint32_t nxt = (k & 1) ? abuf0 : abuf1;
        if (k + 1 < KTAPS) prefetch(k + 1);
        const uint32_t* wtap = a.W + (size_t)k * TAPW;
#pragma unroll
        for (int kt = 0; kt < KTILES; ++kt) {
            uint32_t ah[4], al[4];
#pragma unroll
            for (int j = 0; j < 4; ++j) {
                const uint32_t ao = (uint32_t)(((kt * 4 + j) * 33 + l) * 4);
                ah[j] = lds32(cur + ao);
                al[j] = lds32(cur + ATERM_BYTES + ao);
            }
#pragma unroll
            for (int nt = 0; nt < 8; ++nt) {
                const uint32_t widx = ((kt * 8 + nt) * 32 + l) * 4;
                const uint4 bv = __ldg(reinterpret_cast<const uint4*>(wtap + widx));
                uint32_t bh[2] = {bv.x, bv.y};
                uint32_t bl[2] = {bv.z, bv.w};
                mma_bf16(acc[nt], ah, bh);
                mma_bf16(acc[nt], al, bh);
                mma_bf16(acc[nt], ah, bl);
            }
        }
        if (k + 1 < KTAPS) convert_sts(nxt);
        __syncwarp();
    }

    // ---- epilogue ----
    const int dg = l >> 2, dt = l & 3;
    const int row0 = rowBase + dg;
    const int row1 = row0 + 8;
    if (row0 < nOut) {
        float* o = a.out + (size_t)row0 * 64 + dt * 2;
#pragma unroll
        for (int nt = 0; nt < 8; ++nt)
            *reinterpret_cast<float2*>(o + nt * 8) = make_float2(acc[nt][0], acc[nt][1]);
    }
    if (row1 < nOut) {
        float* o = a.out + (size_t)row1 * 64 + dt * 2;
#pragma unroll
        for (int nt = 0; nt < 8; ++nt)
            *reinterpret_cast<float2*>(o + nt * 8) = make_float2(acc[nt][2], acc[nt][3]);
    }

    if (STATS) {
#pragma unroll
        for (int nt = 0; nt < 8; ++nt) {
#pragma unroll
            for (int j = 0; j < 2; ++j) {
                float ss = acc[nt][j] + acc[nt][j + 2];
                float qq = acc[nt][j] * acc[nt][j] + acc[nt][j + 2] * acc[nt][j + 2];
                ss += __shfl_xor_sync(0xFFFFFFFFu, ss, 4);
                qq += __shfl_xor_sync(0xFFFFFFFFu, qq, 4);
                ss += __shfl_xor_sync(0xFFFFFFFFu, ss, 8);
                qq += __shfl_xor_sync(0xFFFFFFFFu, qq, 8);
                ss += __shfl_xor_sync(0xFFFFFFFFu, ss, 16);
                qq += __shfl_xor_sync(0xFFFFFFFFu, qq, 16);
                if (l < 4) {
                    redS[w][nt * 8 + l * 2 + j] = ss;
                    redQ[w][nt * 8 + l * 2 + j] = qq;
                }
            }
        }
        __syncthreads();
        if (t < 64) {
            float s = 0.f, q = 0.f;
#pragma unroll
            for (int ww = 0; ww < 8; ++ww) { s += redS[ww][t]; q += redQ[ww][t]; }
            a.pS[(size_t)bid * 64 + t] = s;
            a.pQ[(size_t)bid * 64 + t] = q;
        }
        __syncthreads();
        __threadfence();
        if (t == 0) s_last = (atomicAdd(tick, 1u) == (unsigned)nBlocks - 1u) ? 1u : 0u;
        __syncthreads();
        if (s_last) {
            __threadfence();
            const int co = t & 63, sub = t >> 6;
            float s = 0.f, q = 0.f;
            for (int b = sub; b < nBlocks; b += 4) {
                s += a.pS[(size_t)b * 64 + co];
                q += a.pQ[(size_t)b * 64 + co];
            }
            redS[sub][co] = s;
            redQ[sub][co] = q;
            __syncthreads();
            if (t < 64) {
                const float S = (redS[0][t] + redS[1][t]) + (redS[2][t] + redS[3][t]);
                const float Q = (redQ[0][t] + redQ[1][t]) + (redQ[2][t] + redQ[3][t]);
                const float inv = 1.0f / (float)nOut;
                const float m = S * inv;
                const float var = Q * inv - m * m;
                a.st[t] = m;
                a.st[64 + t] = rsqrtf(var + 1e-5f);
            }
            __syncthreads();
            if (t == 0) *tick = 0u;
        }
    }
}

// single conv (pool)
template <int KTILES, int KTAPS>
__global__ void __launch_bounds__(256, 2)
mma_conv_single(ConvArgs a, int nIn, int nOut)
{
    extern __shared__ __align__(16) char smem[];
    conv_body<KTILES, KTAPS, false, false>(a, nIn, nOut, nullptr,
                                           blockIdx.x, gridDim.x, smem);
}

// dual conv: blocks [0,gHalf) run a0, [gHalf,2*gHalf) run a1; both emit stats
template <int KTILES, int KTAPS, bool BN>
__global__ void __launch_bounds__(256, 2)
mma_conv_dual(ConvArgs a0, ConvArgs a1, int nIn, int nOut, int gHalf, unsigned* ticks)
{
    extern __shared__ __align__(16) char smem[];
    if (blockIdx.x < (unsigned)gHalf) {
        conv_body<KTILES, KTAPS, true, BN>(a0, nIn, nOut, &ticks[0],
                                           blockIdx.x, gHalf, smem);
    } else {
        conv_body<KTILES, KTAPS, true, BN>(a1, nIn, nOut, &ticks[1],
                                           blockIdx.x - gHalf, gHalf, smem);
    }
}

// ---------------------------------------------------------------------------
__global__ void combine_kernel(const float4* __restrict__ a, const float* __restrict__ sa,
                               const float4* __restrict__ b, const float* __restrict__ sb,
                               float4* __restrict__ o, long long n4)
{
    const long long i = (long long)blockIdx.x * blockDim.x + threadIdx.x;
    if (i >= n4) return;
    const int c = ((int)(i & 15)) * 4;
    float4 va = a[i];
    float4 vb = b[i];
    float4 r;
    float x;
    x = (va.x - sa[c + 0]) * sa[64 + c + 0]; x = x > 0.f ? x : 0.01f * x; r.x = x;
    x = (va.y - sa[c + 1]) * sa[64 + c + 1]; x = x > 0.f ? x : 0.01f * x; r.y = x;
    x = (va.z - sa[c + 2]) * sa[64 + c + 2]; x = x > 0.f ? x : 0.01f * x; r.z = x;
    x = (va.w - sa[c + 3]) * sa[64 + c + 3]; x = x > 0.f ? x : 0.01f * x; r.w = x;
    x = (vb.x - sb[c + 0]) * sb[64 + c + 0]; x = x > 0.f ? x : 0.01f * x; r.x += x;
    x = (vb.y - sb[c + 1]) * sb[64 + c + 1]; x = x > 0.f ? x : 0.01f * x; r.y += x;
    x = (vb.z - sb[c + 2]) * sb[64 + c + 2]; x = x > 0.f ? x : 0.01f * x; r.z += x;
    x = (vb.w - sb[c + 3]) * sb[64 + c + 3]; x = x > 0.f ? x : 0.01f * x; r.w += x;
    o[i] = r;
}

// out[m] = [x1 | x2 | x3] @ down_w  (fp32 FFMA2 path, warp-autonomous)
__global__ void __launch_bounds__(256)
final_kernel(const float* __restrict__ X1, const float* __restrict__ X2,
             const float* __restrict__ X3, const float* __restrict__ Wp,
             float* __restrict__ out, int M)
{
    __shared__ __align__(16) float buf[8][2][8][64];
    const int t = threadIdx.x;
    const int w = t >> 5;
    const int l = t & 31;
    const int rowBase = (blockIdx.x * 8 + w) * 8;
    const int gr = l >> 2;
    const int gp = l & 3;
    const int grow = rowBase + gr;
    const bool rowOK = (grow < M);

    const float* srcs[3] = {X1, X2, X3};
    auto prefetch = [&](int s, int b) {
        const float* src = srcs[s] + (size_t)(rowOK ? grow : 0) * 64;
        const int sz = rowOK ? 16 : 0;
        const uint32_t dbase = (uint32_t)__cvta_generic_to_shared(&buf[w][b][gr][0]);
#pragma unroll
        for (int i = 0; i < 4; ++i) {
            const int c4 = gp + 4 * i;
            asm volatile("cp.async.ca.shared.global [%0], [%1], 16, %2;\n"
                         :: "r"(dbase + c4 * 16), "l"(src + c4 * 4), "r"(sz));
        }
        asm volatile("cp.async.commit_group;\n");
    };

    u64 accA[8], accB[8];
#pragma unroll
    for (int r = 0; r < 8; ++r) { accA[r] = 0ull; accB[r] = 0ull; }

    prefetch(0, 0);
    for (int s = 0; s < 3; ++s) {
        if (s + 1 < 3) {
            prefetch(s + 1, (s + 1) & 1);
            asm volatile("cp.async.wait_group 1;\n");
        } else {
            asm volatile("cp.async.wait_group 0;\n");
        }
        __syncwarp();
        const float* wk = Wp + (size_t)s * (64 * 64);
        const float* frow = &buf[w][s & 1][0][0];
#pragma unroll
        for (int q = 0; q < 16; ++q) {
            const ulonglong2 wa = *reinterpret_cast<const ulonglong2*>(wk + (q * 64 + l) * 4);
            const ulonglong2 wb = *reinterpret_cast<const ulonglong2*>(wk + (q * 64 + l + 32) * 4);
#pragma unroll
            for (int r = 0; r < 8; ++r) {
                const ulonglong2 s2 =
                    *reinterpret_cast<const ulonglong2*>(frow + r * 64 + q * 4);
                accA[r] = ffma2(s2.x, wa.x, accA[r]);
                accA[r] = ffma2(s2.y, wa.y, accA[r]);
                accB[r] = ffma2(s2.x, wb.x, accB[r]);
                accB[r] = ffma2(s2.y, wb.y, accB[r]);
            }
        }
        __syncwarp();
    }
#pragma unroll
    for (int r = 0; r < 8; ++r) {
        const int orow = rowBase + r;
        if (orow < M) {
            out[(size_t)orow * 64 + l] =
                __uint_as_float((unsigned)accA[r]) + __uint_as_float((unsigned)(accA[r] >> 32));
            out[(size_t)orow * 64 + l + 32] =
                __uint_as_float((unsigned)accB[r]) + __uint_as_float((unsigned)(accB[r] >> 32));
        }
    }
}

// ---------------------------------------------------------------------------
extern "C" void kernel_launch(void* const* d_in, const int* in_sizes, int n_in,
                              void* d_out, int out_size)
{
    const float* feats  = (const float*)d_in[0];
    const float* down_w = (const float*)d_in[14];
    const int* n331_1 = (const int*)d_in[15];
    const int* n313_1 = (const int*)d_in[16];
    const int* pool_n = (const int*)d_in[17];
    const int* n331_2 = (const int*)d_in[18];
    const int* n313_2 = (const int*)d_in[19];
    const int* n331_3 = (const int*)d_in[20];
    const int* n313_3 = (const int*)d_in[21];

    const int N = in_sizes[0] / 32;
    const int M = out_size / 64;

    float *A, *B, *C, *D, *X1, *X2, *X3, *pS, *pQ, *st, *Wt;
    uint32_t* Wb;
    unsigned* ticks;
    cudaGetSymbolAddress((void**)&A,  g_A);
    cudaGetSymbolAddress((void**)&B,  g_B);
    cudaGetSymbolAddress((void**)&C,  g_C);
    cudaGetSymbolAddress((void**)&D,  g_D);
    cudaGetSymbolAddress((void**)&X1, g_X1);
    cudaGetSymbolAddress((void**)&X2, g_X2);
    cudaGetSymbolAddress((void**)&X3, g_X3);
    cudaGetSymbolAddress((void**)&pS, g_pS);
    cudaGetSymbolAddress((void**)&pQ, g_pQ);
    cudaGetSymbolAddress((void**)&st, g_st);
    cudaGetSymbolAddress((void**)&Wt, g_Wt);
    cudaGetSymbolAddress((void**)&Wb, g_Wb);
    cudaGetSymbolAddress((void**)&ticks, g_tick);
    float* st0 = st;
    float* st1 = st + 128;
    float* st2 = st + 256;
    float* st3 = st + 384;
    float* pS1 = pS + (size_t)MAXBLK * 64;
    float* pQ1 = pQ + (size_t)MAXBLK * 64;

    const size_t o0 = 0;
    const size_t o1 = 18432;
    const size_t o2 = 55296;
    const size_t o3 = 73728;
    const size_t o4 = 110592;
    const size_t o5 = 221184;
    const size_t o6 = 258048;
    const size_t o7 = 294912;
    const size_t o8 = 331776;
    const size_t o9 = 368640;
    const size_t o10 = 405504;
    const size_t o11 = 442368;
    const size_t o12 = 479232;

    const int SM2 = 8 * 2 * (2 * 2 * 4 * 33 * 4);   // KTILES=2: 33792
    const int SM4 = 8 * 2 * (2 * 4 * 4 * 33 * 4);   // KTILES=4: 67584
    cudaFuncSetAttribute(mma_conv_dual<2, 9, false>,
                         cudaFuncAttributeMaxDynamicSharedMemorySize, SM2);
    cudaFuncSetAttribute(mma_conv_dual<4, 9, false>,
                         cudaFuncAttributeMaxDynamicSharedMemorySize, SM4);
    cudaFuncSetAttribute(mma_conv_dual<4, 9, true>,
                         cudaFuncAttributeMaxDynamicSharedMemorySize, SM4);
    cudaFuncSetAttribute(mma_conv_single<4, 27>,
                         cudaFuncAttributeMaxDynamicSharedMemorySize, SM4);

    WPtrs wp;
    for (int i = 0; i < 13; ++i) wp.p[i] = (const float*)d_in[1 + i];
    wprep<<<135, 256>>>(wp, Wb);
    wtrans_down<<<3, 256>>>(down_w, Wt);

    const int gN = (N + 127) / 128;
    const int gM = (M + 127) / 128;
    const long long n4N = (long long)N * 16;
    const long long n4M = (long long)M * 16;
    const int gbN = (int)((n4N + 255) / 256);
    const int gbM = (int)((n4M + 255) / 256);
    const int gMf = (M + 63) / 64;

    auto CA = [](const float* in, const int* nbr, const uint32_t* W, float* out,
                 float* ps, float* pq, float* stp, const float* bn) {
        ConvArgs a;
        a.in = in; a.nbr = nbr; a.W = W; a.out = out;
        a.pS = ps; a.pQ = pq; a.st = stp; a.bn = bn;
        return a;
    };

    // ---- block 1 (N rows, 32 -> 64) ----
    mma_conv_dual<2, 9, false><<<2 * gN, 256, SM2>>>(
        CA(feats, n331_1, Wb + o0, A, pS,  pQ,  st0, nullptr),
        CA(feats, n313_1, Wb + o2, C, pS1, pQ1, st2, nullptr),
        N, N, gN, ticks);
    mma_conv_dual<4, 9, true><<<2 * gN, 256, SM4>>>(
        CA(A, n313_1, Wb + o1, B, pS,  pQ,  st1, st0),
        CA(C, n331_1, Wb + o3, D, pS1, pQ1, st3, st2),
        N, N, gN, ticks);
    combine_kernel<<<gbN, 256>>>((const float4*)D, st3, (const float4*)B, st1,
                                 (float4*)C, n4N);

    // ---- pool (K=27): C (N rows) -> X1 (M rows) ----
    mma_conv_single<4, 27><<<gM, 256, SM4>>>(
        CA(C, pool_n, Wb + o4, X1, nullptr, nullptr, nullptr, nullptr), N, M);

    // ---- block 2 (M rows, dilation 2) ----
    mma_conv_dual<4, 9, false><<<2 * gM, 256, SM4>>>(
        CA(X1, n331_2, Wb + o5, A, pS,  pQ,  st0, nullptr),
        CA(X1, n313_2, Wb + o7, C, pS1, pQ1, st2, nullptr),
        M, M, gM, ticks);
    mma_conv_dual<4, 9, true><<<2 * gM, 256, SM4>>>(
        CA(A, n313_2, Wb + o6, B, pS,  pQ,  st1, st0),
        CA(C, n331_2, Wb + o8, D, pS1, pQ1, st3, st2),
        M, M, gM, ticks);
    combine_kernel<<<gbM, 256>>>((const float4*)D, st3, (const float4*)B, st1,
                                 (float4*)X2, n4M);

    // ---- block 3 (M rows, dilation 3) ----
    mma_conv_dual<4, 9, false><<<2 * gM, 256, SM4>>>(
        CA(X2, n331_3, Wb + o9,  A, pS,  pQ,  st0, nullptr),
        CA(X2, n313_3, Wb + o11, C, pS1, pQ1, st2, nullptr),
        M, M, gM, ticks);
    mma_conv_dual<4, 9, true><<<2 * gM, 256, SM4>>>(
        CA(A, n313_3, Wb + o10, B, pS,  pQ,  st1, st0),
        CA(C, n331_3, Wb + o12, D, pS1, pQ1, st3, st2),
        M, M, gM, ticks);
    combine_kernel<<<gbM, 256>>>((const float4*)D, st3, (const float4*)B, st1,
                                 (float4*)X3, n4M);

    // ---- final 1x1 fuse ----
    final_kernel<<<gMf, 256>>>(X1, X2, X3, Wt, (float*)d_out, M);
}

// round 14
// speedup vs baseline: 1.8138x; 1.4877x over previous
#include <cuda_runtime.h>
#include <cuda_bf16.h>
#include <cstdint>

typedef unsigned long long u64;

// ---------------------------------------------------------------------------
// dilate_block — round 14: R13 (dual launches, R10 conv body) + warp-uniform
// sparsity skip: if all 16 rows of a warp have no neighbor for tap k,
// skip gather/convert/MMA for that tap entirely (exactly zero contribution).
// ---------------------------------------------------------------------------

static constexpr int MAXR = 640000;
static constexpr int MAXBLK = MAXR / 128 + 2;

__device__ __align__(16) float g_A [MAXR * 64];
__device__ __align__(16) float g_B [MAXR * 64];
__device__ __align__(16) float g_C [MAXR * 64];
__device__ __align__(16) float g_D [MAXR * 64];
__device__ __align__(16) float g_X1[MAXR * 64];
__device__ __align__(16) float g_X2[MAXR * 64];
__device__ __align__(16) float g_X3[MAXR * 64];
__device__ float g_pS[2 * MAXBLK * 64];
__device__ float g_pQ[2 * MAXBLK * 64];
__device__ float g_st[4 * 128];
__device__ unsigned g_tick[2];                          // zero-init, self-resetting
__device__ __align__(16) float g_Wt[3 * 4096];          // down_w packed (fp32 path)
__device__ __align__(16) uint32_t g_Wb[516096];         // conv weights, frag-major, hi/lo interleaved

// ---------------- helpers ----------------
__device__ __forceinline__ uint32_t smem_u32(const void* p) {
    uint32_t a;
    asm("{ .reg .u64 t; cvta.to.shared.u64 t, %1; cvt.u32.u64 %0, t; }" : "=r"(a) : "l"(p));
    return a;
}
__device__ __forceinline__ uint32_t cvt2(float lo, float hi) {
    uint32_t r;
    asm("cvt.rn.bf16x2.f32 %0, %1, %2;" : "=r"(r) : "f"(hi), "f"(lo));
    return r;
}
__device__ __forceinline__ uint32_t lds32(uint32_t a) {
    uint32_t v;
    asm volatile("ld.shared.b32 %0, [%1];" : "=r"(v) : "r"(a));
    return v;
}
__device__ __forceinline__ void st32(uint32_t a, uint32_t v) {
    asm volatile("st.shared.b32 [%0], %1;" :: "r"(a), "r"(v));
}
__device__ __forceinline__ void mma_bf16(float d[4], const uint32_t a[4], const uint32_t b[2]) {
    asm volatile(
        "mma.sync.aligned.m16n8k16.row.col.f32.bf16.bf16.f32 "
        "{%0,%1,%2,%3}, {%4,%5,%6,%7}, {%8,%9}, {%0,%1,%2,%3};"
        : "+f"(d[0]), "+f"(d[1]), "+f"(d[2]), "+f"(d[3])
        : "r"(a[0]), "r"(a[1]), "r"(a[2]), "r"(a[3]), "r"(b[0]), "r"(b[1]));
}
__device__ __forceinline__ u64 ffma2(u64 a, u64 b, u64 c) {
    u64 d;
    asm("fma.rn.f32x2 %0, %1, %2, %3;" : "=l"(d) : "l"(a), "l"(b), "l"(c));
    return d;
}

// ---------------------------------------------------------------------------
// weight prep: fp32 [K][CIN][64] -> per tap [kt][nt(8)][lane(32)][hi0,hi1,lo0,lo1]
// ---------------------------------------------------------------------------
struct WPtrs { const float* p[13]; };

__global__ void __launch_bounds__(256)
wprep(WPtrs w, uint32_t* __restrict__ dst)
{
    const int nT[13]   = {9,9,9,9,27,9,9,9,9,9,9,9,9};
    const int cinA[13] = {32,64,32,64,64,64,64,64,64,64,64,64,64};
    const int offW[13] = {0,18432,55296,73728,110592,221184,258048,294912,
                          331776,368640,405504,442368,479232};
    int b = blockIdx.x, c = 0;
    while (b >= nT[c]) { b -= nT[c]; ++c; }
    const int CIN = cinA[c];
    const int KT = CIN / 16;
    const float* src = w.p[c] + (size_t)b * CIN * 64;
    uint16_t* tap = reinterpret_cast<uint16_t*>(dst + offW[c] + (size_t)b * (KT * 1024));
    for (int e = threadIdx.x; e < CIN * 64; e += 256) {
        const int ci = e >> 6, co = e & 63;
        const float x = src[e];
        __nv_bfloat16 hb = __float2bfloat16(x);
        __nv_bfloat16 lb = __float2bfloat16(x - __bfloat162float(hb));
        const int kt = ci >> 4, ck = (ci & 15) >> 1, j = ci & 1;
        const int regb = (ck >= 4) ? 1 : 0;
        const int tt = ck & 3, nt = co >> 3, gg = co & 7;
        const int word = (((kt * 8 + nt) * 32 + (gg * 4 + tt)) * 4) + regb;  // hi at +0/+1
        tap[word * 2 + j]       = *reinterpret_cast<unsigned short*>(&hb);
        tap[(word + 2) * 2 + j] = *reinterpret_cast<unsigned short*>(&lb);   // lo at +2/+3
    }
}

__global__ void wtrans_down(const float* __restrict__ src, float* __restrict__ dst)
{
    const int k = blockIdx.x;
    for (int e = threadIdx.x; e < 4096; e += 256) {
        const int ci = e >> 6, co = e & 63;
        dst[k * 4096 + ((ci >> 2) * 64 + co) * 4 + (ci & 3)] = src[k * 4096 + e];
    }
}

// ---------------------------------------------------------------------------
// conv body: one 128-row tile per virtual block bid. Warp-uniform tap skip.
// ---------------------------------------------------------------------------
struct ConvArgs {
    const float* in;
    const int* nbr;
    const uint32_t* W;
    float* out;
    float* pS;
    float* pQ;
    float* st;
    const float* bn;
};

template <int KTILES, int KTAPS, bool STATS, bool BN>
__device__ __forceinline__ void conv_body(
    const ConvArgs a, int nIn, int nOut,
    unsigned* tick, int bid, int nBlocks, char* smem)
{
    constexpr int CIN = KTILES * 16;
    constexpr int TAPW = KTILES * 1024;
    constexpr int ATERM_BYTES = KTILES * 4 * 33 * 4;
    constexpr int ABUF_BYTES = 2 * ATERM_BYTES;
    constexpr int NF4 = CIN / 8;

    __shared__ float redS[8][64];
    __shared__ float redQ[8][64];
    __shared__ float s_st[128];
    __shared__ unsigned s_last;

    const uint32_t abase = smem_u32(smem);
    const int t = threadIdx.x;
    const int w = t >> 5;
    const int l = t & 31;
    const int rowBase = bid * 128 + w * 16;

    if (BN) {
        if (t < 128) s_st[t] = a.bn[t];
        __syncthreads();
    }

    const uint32_t abuf0 = abase + (uint32_t)(w * 2 + 0) * ABUF_BYTES;
    const uint32_t abuf1 = abase + (uint32_t)(w * 2 + 1) * ABUF_BYTES;

    const int gr = l >> 1;
    const int part = l & 1;
    const int grow = rowBase + gr;
    const bool rowOK = (grow < nOut);

    float4 pf[NF4];
    auto getj = [&](int k) -> int {
        return rowOK ? __ldg(&a.nbr[(size_t)k * nOut + grow]) : nIn;
    };
    auto loaddata = [&](int j) {
        if (j < nIn) {
            const float4* s = reinterpret_cast<const float4*>(a.in + (size_t)j * CIN) + part * NF4;
#pragma unroll
            for (int i = 0; i < NF4; ++i) {
                float4 v = s[i];
                if (BN) {
                    const int c4 = (part * NF4 + i) * 4;
                    v.x = (v.x - s_st[c4 + 0]) * s_st[64 + c4 + 0];
                    v.y = (v.y - s_st[c4 + 1]) * s_st[64 + c4 + 1];
                    v.z = (v.z - s_st[c4 + 2]) * s_st[64 + c4 + 2];
                    v.w = (v.w - s_st[c4 + 3]) * s_st[64 + c4 + 3];
                    v.x = v.x > 0.f ? v.x : 0.01f * v.x;
                    v.y = v.y > 0.f ? v.y : 0.01f * v.y;
                    v.z = v.z > 0.f ? v.z : 0.01f * v.z;
                    v.w = v.w > 0.f ? v.w : 0.01f * v.w;
                }
                pf[i] = v;
            }
        } else {
#pragma unroll
            for (int i = 0; i < NF4; ++i) pf[i] = make_float4(0.f, 0.f, 0.f, 0.f);
        }
    };
    auto convert_sts = [&](uint32_t buf) {
#pragma unroll
        for (int i = 0; i < NF4; ++i) {
            const int kt = (KTILES == 4) ? (part * 2 + (i >> 2)) : part;
            const int regb = ((gr >> 3) & 1) | ((i & 2) ? 2 : 0);
            const int lane0 = ((gr & 7) << 2) + ((i & 1) << 1);
            const uint32_t w0 = (uint32_t)(((kt * 4 + regb) * 33 + lane0) * 4);
            const float4 x = pf[i];
            const uint32_t h0 = cvt2(x.x, x.y);
            const uint32_t h1 = cvt2(x.z, x.w);
            const float l0 = x.x - __uint_as_float(h0 << 16);
            const float l1 = x.y - __uint_as_float(h0 & 0xFFFF0000u);
            const float l2 = x.z - __uint_as_float(h1 << 16);
            const float l3 = x.w - __uint_as_float(h1 & 0xFFFF0000u);
            const uint32_t q0 = cvt2(l0, l1);
            const uint32_t q1 = cvt2(l2, l3);
            st32(buf + w0, h0);
            st32(buf + w0 + 4, h1);
            st32(buf + ATERM_BYTES + w0, q0);
            st32(buf + ATERM_BYTES + w0 + 4, q1);
        }
    };

    float acc[8][4];
#pragma unroll
    for (int nt = 0; nt < 8; ++nt)
#pragma unroll
        for (int j = 0; j < 4; ++j) acc[nt][j] = 0.f;

    // tap 0 prologue with skip
    {
        const int j0 = getj(0);
        if (__ballot_sync(0xFFFFFFFFu, j0 < nIn)) {
            loaddata(j0);
            convert_sts(abuf0);
        } else if (0 == KTAPS - 1) {
            // nothing
        }
    }
    bool validCur = true;   // refined below: recompute exact validity of tap 0
    {
        const int j0 = getj(0);
        validCur = (__ballot_sync(0xFFFFFFFFu, j0 < nIn) != 0u);
    }
    __syncwarp();

    for (int k = 0; k < KTAPS; ++k) {
        const uint32_t cur = (k & 1) ? abuf1 : abuf0;
        const uint32_t nxt = (k & 1) ? abuf0 : abuf1;
        bool validNxt = false;
        if (k + 1 < KTAPS) {
            const int jn = getj(k + 1);
            validNxt = (__ballot_sync(0xFFFFFFFFu, jn < nIn) != 0u);
            if (validNxt) loaddata(jn);
        }
        if (validCur) {
            const uint32_t* wtap = a.W + (size_t)k * TAPW;
#pragma unroll
            for (int kt = 0; kt < KTILES; ++kt) {
                uint32_t ah[4], al[4];
#pragma unroll
                for (int j = 0; j < 4; ++j) {
                    const uint32_t ao = (uint32_t)(((kt * 4 + j) * 33 + l) * 4);
                    ah[j] = lds32(cur + ao);
                    al[j] = lds32(cur + ATERM_BYTES + ao);
                }
#pragma unroll
                for (int nt = 0; nt < 8; ++nt) {
                    const uint32_t widx = ((kt * 8 + nt) * 32 + l) * 4;
                    const uint4 bv = __ldg(reinterpret_cast<const uint4*>(wtap + widx));
                    uint32_t bh[2] = {bv.x, bv.y};
                    uint32_t bl[2] = {bv.z, bv.w};
                    mma_bf16(acc[nt], ah, bh);
                    mma_bf16(acc[nt], al, bh);
                    mma_bf16(acc[nt], ah, bl);
                }
            }
        }
        if (k + 1 < KTAPS && validNxt) convert_sts(nxt);
        __syncwarp();
        validCur = validNxt;
    }

    // ---- epilogue ----
    const int dg = l >> 2, dt = l & 3;
    const int row0 = rowBase + dg;
    const int row1 = row0 + 8;
    if (row0 < nOut) {
        float* o = a.out + (size_t)row0 * 64 + dt * 2;
#pragma unroll
        for (int nt = 0; nt < 8; ++nt)
            *reinterpret_cast<float2*>(o + nt * 8) = make_float2(acc[nt][0], acc[nt][1]);
    }
    if (row1 < nOut) {
        float* o = a.out + (size_t)row1 * 64 + dt * 2;
#pragma unroll
        for (int nt = 0; nt < 8; ++nt)
            *reinterpret_cast<float2*>(o + nt * 8) = make_float2(acc[nt][2], acc[nt][3]);
    }

    if (STATS) {
#pragma unroll
        for (int nt = 0; nt < 8; ++nt) {
#pragma unroll
            for (int j = 0; j < 2; ++j) {
                float ss = acc[nt][j] + acc[nt][j + 2];
                float qq = acc[nt][j] * acc[nt][j] + acc[nt][j + 2] * acc[nt][j + 2];
                ss += __shfl_xor_sync(0xFFFFFFFFu, ss, 4);
                qq += __shfl_xor_sync(0xFFFFFFFFu, qq, 4);
                ss += __shfl_xor_sync(0xFFFFFFFFu, ss, 8);
                qq += __shfl_xor_sync(0xFFFFFFFFu, qq, 8);
                ss += __shfl_xor_sync(0xFFFFFFFFu, ss, 16);
                qq += __shfl_xor_sync(0xFFFFFFFFu, qq, 16);
                if (l < 4) {
                    redS[w][nt * 8 + l * 2 + j] = ss;
                    redQ[w][nt * 8 + l * 2 + j] = qq;
                }
            }
        }
        __syncthreads();
        if (t < 64) {
            float s = 0.f, q = 0.f;
#pragma unroll
            for (int ww = 0; ww < 8; ++ww) { s += redS[ww][t]; q += redQ[ww][t]; }
            a.pS[(size_t)bid * 64 + t] = s;
            a.pQ[(size_t)bid * 64 + t] = q;
        }
        __syncthreads();
        __threadfence();
        if (t == 0) s_last = (atomicAdd(tick, 1u) == (unsigned)nBlocks - 1u) ? 1u : 0u;
        __syncthreads();
        if (s_last) {
            __threadfence();
            const int co = t & 63, sub = t >> 6;
            float s = 0.f, q = 0.f;
            for (int b = sub; b < nBlocks; b += 4) {
                s += a.pS[(size_t)b * 64 + co];
                q += a.pQ[(size_t)b * 64 + co];
            }
            redS[sub][co] = s;
            redQ[sub][co] = q;
            __syncthreads();
            if (t < 64) {
                const float S = (redS[0][t] + redS[1][t]) + (redS[2][t] + redS[3][t]);
                const float Q = (redQ[0][t] + redQ[1][t]) + (redQ[2][t] + redQ[3][t]);
                const float inv = 1.0f / (float)nOut;
                const float m = S * inv;
                const float var = Q * inv - m * m;
                a.st[t] = m;
                a.st[64 + t] = rsqrtf(var + 1e-5f);
            }
            __syncthreads();
            if (t == 0) *tick = 0u;
        }
    }
}

// single conv (pool)
template <int KTILES, int KTAPS>
__global__ void __launch_bounds__(256, 2)
mma_conv_single(ConvArgs a, int nIn, int nOut)
{
    extern __shared__ __align__(16) char smem[];
    conv_body<KTILES, KTAPS, false, false>(a, nIn, nOut, nullptr,
                                           blockIdx.x, gridDim.x, smem);
}

// dual conv: blocks [0,gHalf) run a0, [gHalf,2*gHalf) run a1; both emit stats
template <int KTILES, int KTAPS, bool BN>
__global__ void __launch_bounds__(256, 2)
mma_conv_dual(ConvArgs a0, ConvArgs a1, int nIn, int nOut, int gHalf, unsigned* ticks)
{
    extern __shared__ __align__(16) char smem[];
    if (blockIdx.x < (unsigned)gHalf) {
        conv_body<KTILES, KTAPS, true, BN>(a0, nIn, nOut, &ticks[0],
                                           blockIdx.x, gHalf, smem);
    } else {
        conv_body<KTILES, KTAPS, true, BN>(a1, nIn, nOut, &ticks[1],
                                           blockIdx.x - gHalf, gHalf, smem);
    }
}

// ---------------------------------------------------------------------------
__global__ void combine_kernel(const float4* __restrict__ a, const float* __restrict__ sa,
                               const float4* __restrict__ b, const float* __restrict__ sb,
                               float4* __restrict__ o, long long n4)
{
    const long long i = (long long)blockIdx.x * blockDim.x + threadIdx.x;
    if (i >= n4) return;
    const int c = ((int)(i & 15)) * 4;
    float4 va = a[i];
    float4 vb = b[i];
    float4 r;
    float x;
    x = (va.x - sa[c + 0]) * sa[64 + c + 0]; x = x > 0.f ? x : 0.01f * x; r.x = x;
    x = (va.y - sa[c + 1]) * sa[64 + c + 1]; x = x > 0.f ? x : 0.01f * x; r.y = x;
    x = (va.z - sa[c + 2]) * sa[64 + c + 2]; x = x > 0.f ? x : 0.01f * x; r.z = x;
    x = (va.w - sa[c + 3]) * sa[64 + c + 3]; x = x > 0.f ? x : 0.01f * x; r.w = x;
    x = (vb.x - sb[c + 0]) * sb[64 + c + 0]; x = x > 0.f ? x : 0.01f * x; r.x += x;
    x = (vb.y - sb[c + 1]) * sb[64 + c + 1]; x = x > 0.f ? x : 0.01f * x; r.y += x;
    x = (vb.z - sb[c + 2]) * sb[64 + c + 2]; x = x > 0.f ? x : 0.01f * x; r.z += x;
    x = (vb.w - sb[c + 3]) * sb[64 + c + 3]; x = x > 0.f ? x : 0.01f * x; r.w += x;
    o[i] = r;
}

// out[m] = [x1 | x2 | x3] @ down_w  (fp32 FFMA2 path, warp-autonomous)
__global__ void __launch_bounds__(256)
final_kernel(const float* __restrict__ X1, const float* __restrict__ X2,
             const float* __restrict__ X3, const float* __restrict__ Wp,
             float* __restrict__ out, int M)
{
    __shared__ __align__(16) float buf[8][2][8][64];
    const int t = threadIdx.x;
    const int w = t >> 5;
    const int l = t & 31;
    const int rowBase = (blockIdx.x * 8 + w) * 8;
    const int gr = l >> 2;
    const int gp = l & 3;
    const int grow = rowBase + gr;
    const bool rowOK = (grow < M);

    const float* srcs[3] = {X1, X2, X3};
    auto prefetch = [&](int s, int b) {
        const float* src = srcs[s] + (size_t)(rowOK ? grow : 0) * 64;
        const int sz = rowOK ? 16 : 0;
        const uint32_t dbase = (uint32_t)__cvta_generic_to_shared(&buf[w][b][gr][0]);
#pragma unroll
        for (int i = 0; i < 4; ++i) {
            const int c4 = gp + 4 * i;
            asm volatile("cp.async.ca.shared.global [%0], [%1], 16, %2;\n"
                         :: "r"(dbase + c4 * 16), "l"(src + c4 * 4), "r"(sz));
        }
        asm volatile("cp.async.commit_group;\n");
    };

    u64 accA[8], accB[8];
#pragma unroll
    for (int r = 0; r < 8; ++r) { accA[r] = 0ull; accB[r] = 0ull; }

    prefetch(0, 0);
    for (int s = 0; s < 3; ++s) {
        if (s + 1 < 3) {
            prefetch(s + 1, (s + 1) & 1);
            asm volatile("cp.async.wait_group 1;\n");
        } else {
            asm volatile("cp.async.wait_group 0;\n");
        }
        __syncwarp();
        const float* wk = Wp + (size_t)s * (64 * 64);
        const float* frow = &buf[w][s & 1][0][0];
#pragma unroll
        for (int q = 0; q < 16; ++q) {
            const ulonglong2 wa = *reinterpret_cast<const ulonglong2*>(wk + (q * 64 + l) * 4);
            const ulonglong2 wb = *reinterpret_cast<const ulonglong2*>(wk + (q * 64 + l + 32) * 4);
#pragma unroll
            for (int r = 0; r < 8; ++r) {
                const ulonglong2 s2 =
                    *reinterpret_cast<const ulonglong2*>(frow + r * 64 + q * 4);
                accA[r] = ffma2(s2.x, wa.x, accA[r]);
                accA[r] = ffma2(s2.y, wa.y, accA[r]);
                accB[r] = ffma2(s2.x, wb.x, accB[r]);
                accB[r] = ffma2(s2.y, wb.y, accB[r]);
            }
        }
        __syncwarp();
    }
#pragma unroll
    for (int r = 0; r < 8; ++r) {
        const int orow = rowBase + r;
        if (orow < M) {
            out[(size_t)orow * 64 + l] =
                __uint_as_float((unsigned)accA[r]) + __uint_as_float((unsigned)(accA[r] >> 32));
            out[(size_t)orow * 64 + l + 32] =
                __uint_as_float((unsigned)accB[r]) + __uint_as_float((unsigned)(accB[r] >> 32));
        }
    }
}

// ---------------------------------------------------------------------------
extern "C" void kernel_launch(void* const* d_in, const int* in_sizes, int n_in,
                              void* d_out, int out_size)
{
    const float* feats  = (const float*)d_in[0];
    const float* down_w = (const float*)d_in[14];
    const int* n331_1 = (const int*)d_in[15];
    const int* n313_1 = (const int*)d_in[16];
    const int* pool_n = (const int*)d_in[17];
    const int* n331_2 = (const int*)d_in[18];
    const int* n313_2 = (const int*)d_in[19];
    const int* n331_3 = (const int*)d_in[20];
    const int* n313_3 = (const int*)d_in[21];

    const int N = in_sizes[0] / 32;
    const int M = out_size / 64;

    float *A, *B, *C, *D, *X1, *X2, *X3, *pS, *pQ, *st, *Wt;
    uint32_t* Wb;
    unsigned* ticks;
    cudaGetSymbolAddress((void**)&A,  g_A);
    cudaGetSymbolAddress((void**)&B,  g_B);
    cudaGetSymbolAddress((void**)&C,  g_C);
    cudaGetSymbolAddress((void**)&D,  g_D);
    cudaGetSymbolAddress((void**)&X1, g_X1);
    cudaGetSymbolAddress((void**)&X2, g_X2);
    cudaGetSymbolAddress((void**)&X3, g_X3);
    cudaGetSymbolAddress((void**)&pS, g_pS);
    cudaGetSymbolAddress((void**)&pQ, g_pQ);
    cudaGetSymbolAddress((void**)&st, g_st);
    cudaGetSymbolAddress((void**)&Wt, g_Wt);
    cudaGetSymbolAddress((void**)&Wb, g_Wb);
    cudaGetSymbolAddress((void**)&ticks, g_tick);
    float* st0 = st;
    float* st1 = st + 128;
    float* st2 = st + 256;
    float* st3 = st + 384;
    float* pS1 = pS + (size_t)MAXBLK * 64;
    float* pQ1 = pQ + (size_t)MAXBLK * 64;

    const size_t o0 = 0;
    const size_t o1 = 18432;
    const size_t o2 = 55296;
    const size_t o3 = 73728;
    const size_t o4 = 110592;
    const size_t o5 = 221184;
    const size_t o6 = 258048;
    const size_t o7 = 294912;
    const size_t o8 = 331776;
    const size_t o9 = 368640;
    const size_t o10 = 405504;
    const size_t o11 = 442368;
    const size_t o12 = 479232;

    const int SM2 = 8 * 2 * (2 * 2 * 4 * 33 * 4);   // KTILES=2: 33792
    const int SM4 = 8 * 2 * (2 * 4 * 4 * 33 * 4);   // KTILES=4: 67584
    cudaFuncSetAttribute(mma_conv_dual<2, 9, false>,
                         cudaFuncAttributeMaxDynamicSharedMemorySize, SM2);
    cudaFuncSetAttribute(mma_conv_dual<4, 9, false>,
                         cudaFuncAttributeMaxDynamicSharedMemorySize, SM4);
    cudaFuncSetAttribute(mma_conv_dual<4, 9, true>,
                         cudaFuncAttributeMaxDynamicSharedMemorySize, SM4);
    cudaFuncSetAttribute(mma_conv_single<4, 27>,
                         cudaFuncAttributeMaxDynamicSharedMemorySize, SM4);

    WPtrs wp;
    for (int i = 0; i < 13; ++i) wp.p[i] = (const float*)d_in[1 + i];
    wprep<<<135, 256>>>(wp, Wb);
    wtrans_down<<<3, 256>>>(down_w, Wt);

    const int gN = (N + 127) / 128;
    const int gM = (M + 127) / 128;
    const long long n4N = (long long)N * 16;
    const long long n4M = (long long)M * 16;
    const int gbN = (int)((n4N + 255) / 256);
    const int gbM = (int)((n4M + 255) / 256);
    const int gMf = (M + 63) / 64;

    auto CA = [](const float* in, const int* nbr, const uint32_t* W, float* out,
                 float* ps, float* pq, float* stp, const float* bn) {
        ConvArgs a;
        a.in = in; a.nbr = nbr; a.W = W; a.out = out;
        a.pS = ps; a.pQ = pq; a.st = stp; a.bn = bn;
        return a;
    };

    // ---- block 1 (N rows, 32 -> 64) ----
    mma_conv_dual<2, 9, false><<<2 * gN, 256, SM2>>>(
        CA(feats, n331_1, Wb + o0, A, pS,  pQ,  st0, nullptr),
        CA(feats, n313_1, Wb + o2, C, pS1, pQ1, st2, nullptr),
        N, N, gN, ticks);
    mma_conv_dual<4, 9, true><<<2 * gN, 256, SM4>>>(
        CA(A, n313_1, Wb + o1, B, pS,  pQ,  st1, st0),
        CA(C, n331_1, Wb + o3, D, pS1, pQ1, st3, st2),
        N, N, gN, ticks);
    combine_kernel<<<gbN, 256>>>((const float4*)D, st3, (const float4*)B, st1,
                                 (float4*)C, n4N);

    // ---- pool (K=27): C (N rows) -> X1 (M rows) ----
    mma_conv_single<4, 27><<<gM, 256, SM4>>>(
        CA(C, pool_n, Wb + o4, X1, nullptr, nullptr, nullptr, nullptr), N, M);

    // ---- block 2 (M rows, dilation 2) ----
    mma_conv_dual<4, 9, false><<<2 * gM, 256, SM4>>>(
        CA(X1, n331_2, Wb + o5, A, pS,  pQ,  st0, nullptr),
        CA(X1, n313_2, Wb + o7, C, pS1, pQ1, st2, nullptr),
        M, M, gM, ticks);
    mma_conv_dual<4, 9, true><<<2 * gM, 256, SM4>>>(
        CA(A, n313_2, Wb + o6, B, pS,  pQ,  st1, st0),
        CA(C, n331_2, Wb + o8, D, pS1, pQ1, st3, st2),
        M, M, gM, ticks);
    combine_kernel<<<gbM, 256>>>((const float4*)D, st3, (const float4*)B, st1,
                                 (float4*)X2, n4M);

    // ---- block 3 (M rows, dilation 3) ----
    mma_conv_dual<4, 9, false><<<2 * gM, 256, SM4>>>(
        CA(X2, n331_3, Wb + o9,  A, pS,  pQ,  st0, nullptr),
        CA(X2, n313_3, Wb + o11, C, pS1, pQ1, st2, nullptr),
        M, M, gM, ticks);
    mma_conv_dual<4, 9, true><<<2 * gM, 256, SM4>>>(
        CA(A, n313_3, Wb + o10, B, pS,  pQ,  st1, st0),
        CA(C, n331_3, Wb + o12, D, pS1, pQ1, st3, st2),
        M, M, gM, ticks);
    combine_kernel<<<gbM, 256>>>((const float4*)D, st3, (const float4*)B, st1,
                                 (float4*)X3, n4M);

    // ---- final 1x1 fuse ----
    final_kernel<<<gMf, 256>>>(X1, X2, X3, Wt, (float*)d_out, M);
}

// round 15
// speedup vs baseline: 1.8829x; 1.0381x over previous
#include <cuda_runtime.h>
#include <cuda_bf16.h>
#include <cstdint>

typedef unsigned long long u64;

// ---------------------------------------------------------------------------
// dilate_block — round 15: R14 + precomputed warp validity mask:
//   nbr indices loaded in batches of 9 (high MLP, one latency exposure),
//   ballots folded into a register bitmask; skipped taps cost ~2 instrs.
// ---------------------------------------------------------------------------

static constexpr int MAXR = 640000;
static constexpr int MAXBLK = MAXR / 128 + 2;

__device__ __align__(16) float g_A [MAXR * 64];
__device__ __align__(16) float g_B [MAXR * 64];
__device__ __align__(16) float g_C [MAXR * 64];
__device__ __align__(16) float g_D [MAXR * 64];
__device__ __align__(16) float g_X1[MAXR * 64];
__device__ __align__(16) float g_X2[MAXR * 64];
__device__ __align__(16) float g_X3[MAXR * 64];
__device__ float g_pS[2 * MAXBLK * 64];
__device__ float g_pQ[2 * MAXBLK * 64];
__device__ float g_st[4 * 128];
__device__ unsigned g_tick[2];                          // zero-init, self-resetting
__device__ __align__(16) float g_Wt[3 * 4096];          // down_w packed (fp32 path)
__device__ __align__(16) uint32_t g_Wb[516096];         // conv weights, frag-major, hi/lo interleaved

// ---------------- helpers ----------------
__device__ __forceinline__ uint32_t smem_u32(const void* p) {
    uint32_t a;
    asm("{ .reg .u64 t; cvta.to.shared.u64 t, %1; cvt.u32.u64 %0, t; }" : "=r"(a) : "l"(p));
    return a;
}
__device__ __forceinline__ uint32_t cvt2(float lo, float hi) {
    uint32_t r;
    asm("cvt.rn.bf16x2.f32 %0, %1, %2;" : "=r"(r) : "f"(hi), "f"(lo));
    return r;
}
__device__ __forceinline__ uint32_t lds32(uint32_t a) {
    uint32_t v;
    asm volatile("ld.shared.b32 %0, [%1];" : "=r"(v) : "r"(a));
    return v;
}
__device__ __forceinline__ void st32(uint32_t a, uint32_t v) {
    asm volatile("st.shared.b32 [%0], %1;" :: "r"(a), "r"(v));
}
__device__ __forceinline__ void mma_bf16(float d[4], const uint32_t a[4], const uint32_t b[2]) {
    asm volatile(
        "mma.sync.aligned.m16n8k16.row.col.f32.bf16.bf16.f32 "
        "{%0,%1,%2,%3}, {%4,%5,%6,%7}, {%8,%9}, {%0,%1,%2,%3};"
        : "+f"(d[0]), "+f"(d[1]), "+f"(d[2]), "+f"(d[3])
        : "r"(a[0]), "r"(a[1]), "r"(a[2]), "r"(a[3]), "r"(b[0]), "r"(b[1]));
}
__device__ __forceinline__ u64 ffma2(u64 a, u64 b, u64 c) {
    u64 d;
    asm("fma.rn.f32x2 %0, %1, %2, %3;" : "=l"(d) : "l"(a), "l"(b), "l"(c));
    return d;
}

// ---------------------------------------------------------------------------
// weight prep: fp32 [K][CIN][64] -> per tap [kt][nt(8)][lane(32)][hi0,hi1,lo0,lo1]
// ---------------------------------------------------------------------------
struct WPtrs { const float* p[13]; };

__global__ void __launch_bounds__(256)
wprep(WPtrs w, uint32_t* __restrict__ dst)
{
    const int nT[13]   = {9,9,9,9,27,9,9,9,9,9,9,9,9};
    const int cinA[13] = {32,64,32,64,64,64,64,64,64,64,64,64,64};
    const int offW[13] = {0,18432,55296,73728,110592,221184,258048,294912,
                          331776,368640,405504,442368,479232};
    int b = blockIdx.x, c = 0;
    while (b >= nT[c]) { b -= nT[c]; ++c; }
    const int CIN = cinA[c];
    const int KT = CIN / 16;
    const float* src = w.p[c] + (size_t)b * CIN * 64;
    uint16_t* tap = reinterpret_cast<uint16_t*>(dst + offW[c] + (size_t)b * (KT * 1024));
    for (int e = threadIdx.x; e < CIN * 64; e += 256) {
        const int ci = e >> 6, co = e & 63;
        const float x = src[e];
        __nv_bfloat16 hb = __float2bfloat16(x);
        __nv_bfloat16 lb = __float2bfloat16(x - __bfloat162float(hb));
        const int kt = ci >> 4, ck = (ci & 15) >> 1, j = ci & 1;
        const int regb = (ck >= 4) ? 1 : 0;
        const int tt = ck & 3, nt = co >> 3, gg = co & 7;
        const int word = (((kt * 8 + nt) * 32 + (gg * 4 + tt)) * 4) + regb;  // hi at +0/+1
        tap[word * 2 + j]       = *reinterpret_cast<unsigned short*>(&hb);
        tap[(word + 2) * 2 + j] = *reinterpret_cast<unsigned short*>(&lb);   // lo at +2/+3
    }
}

__global__ void wtrans_down(const float* __restrict__ src, float* __restrict__ dst)
{
    const int k = blockIdx.x;
    for (int e = threadIdx.x; e < 4096; e += 256) {
        const int ci = e >> 6, co = e & 63;
        dst[k * 4096 + ((ci >> 2) * 64 + co) * 4 + (ci & 3)] = src[k * 4096 + e];
    }
}

// ---------------------------------------------------------------------------
// conv body: one 128-row tile per virtual block bid. Masked tap skip.
// ---------------------------------------------------------------------------
struct ConvArgs {
    const float* in;
    const int* nbr;
    const uint32_t* W;
    float* out;
    float* pS;
    float* pQ;
    float* st;
    const float* bn;
};

template <int KTILES, int KTAPS, bool STATS, bool BN>
__device__ __forceinline__ void conv_body(
    const ConvArgs a, int nIn, int nOut,
    unsigned* tick, int bid, int nBlocks, char* smem)
{
    constexpr int CIN = KTILES * 16;
    constexpr int TAPW = KTILES * 1024;
    constexpr int ATERM_BYTES = KTILES * 4 * 33 * 4;
    constexpr int ABUF_BYTES = 2 * ATERM_BYTES;
    constexpr int NF4 = CIN / 8;

    __shared__ float redS[8][64];
    __shared__ float redQ[8][64];
    __shared__ float s_st[128];
    __shared__ unsigned s_last;

    const uint32_t abase = smem_u32(smem);
    const int t = threadIdx.x;
    const int w = t >> 5;
    const int l = t & 31;
    const int rowBase = bid * 128 + w * 16;

    if (BN) {
        if (t < 128) s_st[t] = a.bn[t];
        __syncthreads();
    }

    const uint32_t abuf0 = abase + (uint32_t)(w * 2 + 0) * ABUF_BYTES;
    const uint32_t abuf1 = abase + (uint32_t)(w * 2 + 1) * ABUF_BYTES;

    const int gr = l >> 1;
    const int part = l & 1;
    const int grow = rowBase + gr;
    const bool rowOK = (grow < nOut);

    float4 pf[NF4];
    auto getj = [&](int k) -> int {
        return rowOK ? __ldg(&a.nbr[(size_t)k * nOut + grow]) : nIn;
    };
    auto loaddata = [&](int j) {
        if (j < nIn) {
            const float4* s = reinterpret_cast<const float4*>(a.in + (size_t)j * CIN) + part * NF4;
#pragma unroll
            for (int i = 0; i < NF4; ++i) {
                float4 v = s[i];
                if (BN) {
                    const int c4 = (part * NF4 + i) * 4;
                    v.x = (v.x - s_st[c4 + 0]) * s_st[64 + c4 + 0];
                    v.y = (v.y - s_st[c4 + 1]) * s_st[64 + c4 + 1];
                    v.z = (v.z - s_st[c4 + 2]) * s_st[64 + c4 + 2];
                    v.w = (v.w - s_st[c4 + 3]) * s_st[64 + c4 + 3];
                    v.x = v.x > 0.f ? v.x : 0.01f * v.x;
                    v.y = v.y > 0.f ? v.y : 0.01f * v.y;
                    v.z = v.z > 0.f ? v.z : 0.01f * v.z;
                    v.w = v.w > 0.f ? v.w : 0.01f * v.w;
                }
                pf[i] = v;
            }
        } else {
#pragma unroll
            for (int i = 0; i < NF4; ++i) pf[i] = make_float4(0.f, 0.f, 0.f, 0.f);
        }
    };
    auto convert_sts = [&](uint32_t buf) {
#pragma unroll
        for (int i = 0; i < NF4; ++i) {
            const int kt = (KTILES == 4) ? (part * 2 + (i >> 2)) : part;
            const int regb = ((gr >> 3) & 1) | ((i & 2) ? 2 : 0);
            const int lane0 = ((gr & 7) << 2) + ((i & 1) << 1);
            const uint32_t w0 = (uint32_t)(((kt * 4 + regb) * 33 + lane0) * 4);
            const float4 x = pf[i];
            const uint32_t h0 = cvt2(x.x, x.y);
            const uint32_t h1 = cvt2(x.z, x.w);
            const float l0 = x.x - __uint_as_float(h0 << 16);
            const float l1 = x.y - __uint_as_float(h0 & 0xFFFF0000u);
            const float l2 = x.z - __uint_as_float(h1 << 16);
            const float l3 = x.w - __uint_as_float(h1 & 0xFFFF0000u);
            const uint32_t q0 = cvt2(l0, l1);
            const uint32_t q1 = cvt2(l2, l3);
            st32(buf + w0, h0);
            st32(buf + w0 + 4, h1);
            st32(buf + ATERM_BYTES + w0, q0);
            st32(buf + ATERM_BYTES + w0 + 4, q1);
        }
    };

    // ---- prologue: batched validity mask (chunks of 9 -> one latency hit) ----
    unsigned vmask = 0;
#pragma unroll
    for (int c0 = 0; c0 < KTAPS; c0 += 9) {
        int jj[9];
#pragma unroll
        for (int i = 0; i < 9; ++i)
            if (c0 + i < KTAPS) jj[i] = getj(c0 + i);
#pragma unroll
        for (int i = 0; i < 9; ++i)
            if (c0 + i < KTAPS)
                if (__ballot_sync(0xFFFFFFFFu, jj[i] < nIn)) vmask |= 1u << (c0 + i);
    }

    float acc[8][4];
#pragma unroll
    for (int nt = 0; nt < 8; ++nt)
#pragma unroll
        for (int j = 0; j < 4; ++j) acc[nt][j] = 0.f;

    if (vmask & 1u) {
        loaddata(getj(0));          // nbr line now L1-resident
        convert_sts(abuf0);
    }
    __syncwarp();

    for (int k = 0; k < KTAPS; ++k) {
        const uint32_t cur = (k & 1) ? abuf1 : abuf0;
        const uint32_t nxt = (k & 1) ? abuf0 : abuf1;
        const bool validCur = (vmask >> k) & 1u;
        const bool validNxt = (k + 1 < KTAPS) && ((vmask >> (k + 1)) & 1u);
        if (validNxt) loaddata(getj(k + 1));
        if (validCur) {
            const uint32_t* wtap = a.W + (size_t)k * TAPW;
#pragma unroll
            for (int kt = 0; kt < KTILES; ++kt) {
                uint32_t ah[4], al[4];
#pragma unroll
                for (int j = 0; j < 4; ++j) {
                    const uint32_t ao = (uint32_t)(((kt * 4 + j) * 33 + l) * 4);
                    ah[j] = lds32(cur + ao);
                    al[j] = lds32(cur + ATERM_BYTES + ao);
                }
#pragma unroll
                for (int nt = 0; nt < 8; ++nt) {
                    const uint32_t widx = ((kt * 8 + nt) * 32 + l) * 4;
                    const uint4 bv = __ldg(reinterpret_cast<const uint4*>(wtap + widx));
                    uint32_t bh[2] = {bv.x, bv.y};
                    uint32_t bl[2] = {bv.z, bv.w};
                    mma_bf16(acc[nt], ah, bh);
                    mma_bf16(acc[nt], al, bh);
                    mma_bf16(acc[nt], ah, bl);
                }
            }
        }
        if (validNxt) convert_sts(nxt);
        __syncwarp();
    }

    // ---- epilogue ----
    const int dg = l >> 2, dt = l & 3;
    const int row0 = rowBase + dg;
    const int row1 = row0 + 8;
    if (row0 < nOut) {
        float* o = a.out + (size_t)row0 * 64 + dt * 2;
#pragma unroll
        for (int nt = 0; nt < 8; ++nt)
            *reinterpret_cast<float2*>(o + nt * 8) = make_float2(acc[nt][0], acc[nt][1]);
    }
    if (row1 < nOut) {
        float* o = a.out + (size_t)row1 * 64 + dt * 2;
#pragma unroll
        for (int nt = 0; nt < 8; ++nt)
            *reinterpret_cast<float2*>(o + nt * 8) = make_float2(acc[nt][2], acc[nt][3]);
    }

    if (STATS) {
#pragma unroll
        for (int nt = 0; nt < 8; ++nt) {
#pragma unroll
            for (int j = 0; j < 2; ++j) {
                float ss = acc[nt][j] + acc[nt][j + 2];
                float qq = acc[nt][j] * acc[nt][j] + acc[nt][j + 2] * acc[nt][j + 2];
                ss += __shfl_xor_sync(0xFFFFFFFFu, ss, 4);
                qq += __shfl_xor_sync(0xFFFFFFFFu, qq, 4);
                ss += __shfl_xor_sync(0xFFFFFFFFu, ss, 8);
                qq += __shfl_xor_sync(0xFFFFFFFFu, qq, 8);
                ss += __shfl_xor_sync(0xFFFFFFFFu, ss, 16);
                qq += __shfl_xor_sync(0xFFFFFFFFu, qq, 16);
                if (l < 4) {
                    redS[w][nt * 8 + l * 2 + j] = ss;
                    redQ[w][nt * 8 + l * 2 + j] = qq;
                }
            }
        }
        __syncthreads();
        if (t < 64) {
            float s = 0.f, q = 0.f;
#pragma unroll
            for (int ww = 0; ww < 8; ++ww) { s += redS[ww][t]; q += redQ[ww][t]; }
            a.pS[(size_t)bid * 64 + t] = s;
            a.pQ[(size_t)bid * 64 + t] = q;
        }
        __syncthreads();
        __threadfence();
        if (t == 0) s_last = (atomicAdd(tick, 1u) == (unsigned)nBlocks - 1u) ? 1u : 0u;
        __syncthreads();
        if (s_last) {
            __threadfence();
            const int co = t & 63, sub = t >> 6;
            float s = 0.f, q = 0.f;
            for (int b = sub; b < nBlocks; b += 4) {
                s += a.pS[(size_t)b * 64 + co];
                q += a.pQ[(size_t)b * 64 + co];
            }
            redS[sub][co] = s;
            redQ[sub][co] = q;
            __syncthreads();
            if (t < 64) {
                const float S = (redS[0][t] + redS[1][t]) + (redS[2][t] + redS[3][t]);
                const float Q = (redQ[0][t] + redQ[1][t]) + (redQ[2][t] + redQ[3][t]);
                const float inv = 1.0f / (float)nOut;
                const float m = S * inv;
                const float var = Q * inv - m * m;
                a.st[t] = m;
                a.st[64 + t] = rsqrtf(var + 1e-5f);
            }
            __syncthreads();
            if (t == 0) *tick = 0u;
        }
    }
}

// single conv (pool)
template <int KTILES, int KTAPS>
__global__ void __launch_bounds__(256, 2)
mma_conv_single(ConvArgs a, int nIn, int nOut)
{
    extern __shared__ __align__(16) char smem[];
    conv_body<KTILES, KTAPS, false, false>(a, nIn, nOut, nullptr,
                                           blockIdx.x, gridDim.x, smem);
}

// dual conv: blocks [0,gHalf) run a0, [gHalf,2*gHalf) run a1; both emit stats
template <int KTILES, int KTAPS, bool BN>
__global__ void __launch_bounds__(256, 2)
mma_conv_dual(ConvArgs a0, ConvArgs a1, int nIn, int nOut, int gHalf, unsigned* ticks)
{
    extern __shared__ __align__(16) char smem[];
    if (blockIdx.x < (unsigned)gHalf) {
        conv_body<KTILES, KTAPS, true, BN>(a0, nIn, nOut, &ticks[0],
                                           blockIdx.x, gHalf, smem);
    } else {
        conv_body<KTILES, KTAPS, true, BN>(a1, nIn, nOut, &ticks[1],
                                           blockIdx.x - gHalf, gHalf, smem);
    }
}

// ---------------------------------------------------------------------------
__global__ void combine_kernel(const float4* __restrict__ a, const float* __restrict__ sa,
                               const float4* __restrict__ b, const float* __restrict__ sb,
                               float4* __restrict__ o, long long n4)
{
    const long long i = (long long)blockIdx.x * blockDim.x + threadIdx.x;
    if (i >= n4) return;
    const int c = ((int)(i & 15)) * 4;
    float4 va = a[i];
    float4 vb = b[i];
    float4 r;
    float x;
    x = (va.x - sa[c + 0]) * sa[64 + c + 0]; x = x > 0.f ? x : 0.01f * x; r.x = x;
    x = (va.y - sa[c + 1]) * sa[64 + c + 1]; x = x > 0.f ? x : 0.01f * x; r.y = x;
    x = (va.z - sa[c + 2]) * sa[64 + c + 2]; x = x > 0.f ? x : 0.01f * x; r.z = x;
    x = (va.w - sa[c + 3]) * sa[64 + c + 3]; x = x > 0.f ? x : 0.01f * x; r.w = x;
    x = (vb.x - sb[c + 0]) * sb[64 + c + 0]; x = x > 0.f ? x : 0.01f * x; r.x += x;
    x = (vb.y - sb[c + 1]) * sb[64 + c + 1]; x = x > 0.f ? x : 0.01f * x; r.y += x;
    x = (vb.z - sb[c + 2]) * sb[64 + c + 2]; x = x > 0.f ? x : 0.01f * x; r.z += x;
    x = (vb.w - sb[c + 3]) * sb[64 + c + 3]; x = x > 0.f ? x : 0.01f * x; r.w += x;
    o[i] = r;
}

// out[m] = [x1 | x2 | x3] @ down_w  (fp32 FFMA2 path, warp-autonomous)
__global__ void __launch_bounds__(256)
final_kernel(const float* __restrict__ X1, const float* __restrict__ X2,
             const float* __restrict__ X3, const float* __restrict__ Wp,
             float* __restrict__ out, int M)
{
    __shared__ __align__(16) float buf[8][2][8][64];
    const int t = threadIdx.x;
    const int w = t >> 5;
    const int l = t & 31;
    const int rowBase = (blockIdx.x * 8 + w) * 8;
    const int gr = l >> 2;
    const int gp = l & 3;
    const int grow = rowBase + gr;
    const bool rowOK = (grow < M);

    const float* srcs[3] = {X1, X2, X3};
    auto prefetch = [&](int s, int b) {
        const float* src = srcs[s] + (size_t)(rowOK ? grow : 0) * 64;
        const int sz = rowOK ? 16 : 0;
        const uint32_t dbase = (uint32_t)__cvta_generic_to_shared(&buf[w][b][gr][0]);
#pragma unroll
        for (int i = 0; i < 4; ++i) {
            const int c4 = gp + 4 * i;
            asm volatile("cp.async.ca.shared.global [%0], [%1], 16, %2;\n"
                         :: "r"(dbase + c4 * 16), "l"(src + c4 * 4), "r"(sz));
        }
        asm volatile("cp.async.commit_group;\n");
    };

    u64 accA[8], accB[8];
#pragma unroll
    for (int r = 0; r < 8; ++r) { accA[r] = 0ull; accB[r] = 0ull; }

    prefetch(0, 0);
    for (int s = 0; s < 3; ++s) {
        if (s + 1 < 3) {
            prefetch(s + 1, (s + 1) & 1);
            asm volatile("cp.async.wait_group 1;\n");
        } else {
            asm volatile("cp.async.wait_group 0;\n");
        }
        __syncwarp();
        const float* wk = Wp + (size_t)s * (64 * 64);
        const float* frow = &buf[w][s & 1][0][0];
#pragma unroll
        for (int q = 0; q < 16; ++q) {
            const ulonglong2 wa = *reinterpret_cast<const ulonglong2*>(wk + (q * 64 + l) * 4);
            const ulonglong2 wb = *reinterpret_cast<const ulonglong2*>(wk + (q * 64 + l + 32) * 4);
#pragma unroll
            for (int r = 0; r < 8; ++r) {
                const ulonglong2 s2 =
                    *reinterpret_cast<const ulonglong2*>(frow + r * 64 + q * 4);
                accA[r] = ffma2(s2.x, wa.x, accA[r]);
                accA[r] = ffma2(s2.y, wa.y, accA[r]);
                accB[r] = ffma2(s2.x, wb.x, accB[r]);
                accB[r] = ffma2(s2.y, wb.y, accB[r]);
            }
        }
        __syncwarp();
    }
#pragma unroll
    for (int r = 0; r < 8; ++r) {
        const int orow = rowBase + r;
        if (orow < M) {
            out[(size_t)orow * 64 + l] =
                __uint_as_float((unsigned)accA[r]) + __uint_as_float((unsigned)(accA[r] >> 32));
            out[(size_t)orow * 64 + l + 32] =
                __uint_as_float((unsigned)accB[r]) + __uint_as_float((unsigned)(accB[r] >> 32));
        }
    }
}

// ---------------------------------------------------------------------------
extern "C" void kernel_launch(void* const* d_in, const int* in_sizes, int n_in,
                              void* d_out, int out_size)
{
    const float* feats  = (const float*)d_in[0];
    const float* down_w = (const float*)d_in[14];
    const int* n331_1 = (const int*)d_in[15];
    const int* n313_1 = (const int*)d_in[16];
    const int* pool_n = (const int*)d_in[17];
    const int* n331_2 = (const int*)d_in[18];
    const int* n313_2 = (const int*)d_in[19];
    const int* n331_3 = (const int*)d_in[20];
    const int* n313_3 = (const int*)d_in[21];

    const int N = in_sizes[0] / 32;
    const int M = out_size / 64;

    float *A, *B, *C, *D, *X1, *X2, *X3, *pS, *pQ, *st, *Wt;
    uint32_t* Wb;
    unsigned* ticks;
    cudaGetSymbolAddress((void**)&A,  g_A);
    cudaGetSymbolAddress((void**)&B,  g_B);
    cudaGetSymbolAddress((void**)&C,  g_C);
    cudaGetSymbolAddress((void**)&D,  g_D);
    cudaGetSymbolAddress((void**)&X1, g_X1);
    cudaGetSymbolAddress((void**)&X2, g_X2);
    cudaGetSymbolAddress((void**)&X3, g_X3);
    cudaGetSymbolAddress((void**)&pS, g_pS);
    cudaGetSymbolAddress((void**)&pQ, g_pQ);
    cudaGetSymbolAddress((void**)&st, g_st);
    cudaGetSymbolAddress((void**)&Wt, g_Wt);
    cudaGetSymbolAddress((void**)&Wb, g_Wb);
    cudaGetSymbolAddress((void**)&ticks, g_tick);
    float* st0 = st;
    float* st1 = st + 128;
    float* st2 = st + 256;
    float* st3 = st + 384;
    float* pS1 = pS + (size_t)MAXBLK * 64;
    float* pQ1 = pQ + (size_t)MAXBLK * 64;

    const size_t o0 = 0;
    const size_t o1 = 18432;
    const size_t o2 = 55296;
    const size_t o3 = 73728;
    const size_t o4 = 110592;
    const size_t o5 = 221184;
    const size_t o6 = 258048;
    const size_t o7 = 294912;
    const size_t o8 = 331776;
    const size_t o9 = 368640;
    const size_t o10 = 405504;
    const size_t o11 = 442368;
    const size_t o12 = 479232;

    const int SM2 = 8 * 2 * (2 * 2 * 4 * 33 * 4);   // KTILES=2: 33792
    const int SM4 = 8 * 2 * (2 * 4 * 4 * 33 * 4);   // KTILES=4: 67584
    cudaFuncSetAttribute(mma_conv_dual<2, 9, false>,
                         cudaFuncAttributeMaxDynamicSharedMemorySize, SM2);
    cudaFuncSetAttribute(mma_conv_dual<4, 9, false>,
                         cudaFuncAttributeMaxDynamicSharedMemorySize, SM4);
    cudaFuncSetAttribute(mma_conv_dual<4, 9, true>,
                         cudaFuncAttributeMaxDynamicSharedMemorySize, SM4);
    cudaFuncSetAttribute(mma_conv_single<4, 27>,
                         cudaFuncAttributeMaxDynamicSharedMemorySize, SM4);

    WPtrs wp;
    for (int i = 0; i < 13; ++i) wp.p[i] = (const float*)d_in[1 + i];
    wprep<<<135, 256>>>(wp, Wb);
    wtrans_down<<<3, 256>>>(down_w, Wt);

    const int gN = (N + 127) / 128;
    const int gM = (M + 127) / 128;
    const long long n4N = (long long)N * 16;
    const long long n4M = (long long)M * 16;
    const int gbN = (int)((n4N + 255) / 256);
    const int gbM = (int)((n4M + 255) / 256);
    const int gMf = (M + 63) / 64;

    auto CA = [](const float* in, const int* nbr, const uint32_t* W, float* out,
                 float* ps, float* pq, float* stp, const float* bn) {
        ConvArgs a;
        a.in = in; a.nbr = nbr; a.W = W; a.out = out;
        a.pS = ps; a.pQ = pq; a.st = stp; a.bn = bn;
        return a;
    };

    // ---- block 1 (N rows, 32 -> 64) ----
    mma_conv_dual<2, 9, false><<<2 * gN, 256, SM2>>>(
        CA(feats, n331_1, Wb + o0, A, pS,  pQ,  st0, nullptr),
        CA(feats, n313_1, Wb + o2, C, pS1, pQ1, st2, nullptr),
        N, N, gN, ticks);
    mma_conv_dual<4, 9, true><<<2 * gN, 256, SM4>>>(
        CA(A, n313_1, Wb + o1, B, pS,  pQ,  st1, st0),
        CA(C, n331_1, Wb + o3, D, pS1, pQ1, st3, st2),
        N, N, gN, ticks);
    combine_kernel<<<gbN, 256>>>((const float4*)D, st3, (const float4*)B, st1,
                                 (float4*)C, n4N);

    // ---- pool (K=27): C (N rows) -> X1 (M rows) ----
    mma_conv_single<4, 27><<<gM, 256, SM4>>>(
        CA(C, pool_n, Wb + o4, X1, nullptr, nullptr, nullptr, nullptr), N, M);

    // ---- block 2 (M rows, dilation 2) ----
    mma_conv_dual<4, 9, false><<<2 * gM, 256, SM4>>>(
        CA(X1, n331_2, Wb + o5, A, pS,  pQ,  st0, nullptr),
        CA(X1, n313_2, Wb + o7, C, pS1, pQ1, st2, nullptr),
        M, M, gM, ticks);
    mma_conv_dual<4, 9, true><<<2 * gM, 256, SM4>>>(
        CA(A, n313_2, Wb + o6, B, pS,  pQ,  st1, st0),
        CA(C, n331_2, Wb + o8, D, pS1, pQ1, st3, st2),
        M, M, gM, ticks);
    combine_kernel<<<gbM, 256>>>((const float4*)D, st3, (const float4*)B, st1,
                                 (float4*)X2, n4M);

    // ---- block 3 (M rows, dilation 3) ----
    mma_conv_dual<4, 9, false><<<2 * gM, 256, SM4>>>(
        CA(X2, n331_3, Wb + o9,  A, pS,  pQ,  st0, nullptr),
        CA(X2, n313_3, Wb + o11, C, pS1, pQ1, st2, nullptr),
        M, M, gM, ticks);
    mma_conv_dual<4, 9, true><<<2 * gM, 256, SM4>>>(
        CA(A, n313_3, Wb + o10, B, pS,  pQ,  st1, st0),
        CA(C, n331_3, Wb + o12, D, pS1, pQ1, st3, st2),
        M, M, gM, ticks);
    combine_kernel<<<gbM, 256>>>((const float4*)D, st3, (const float4*)B, st1,
                                 (float4*)X3, n4M);

    // ---- final 1x1 fuse ----
    final_kernel<<<gMf, 256>>>(X1, X2, X3, Wt, (float*)d_out, M);
}

// round 16
// speedup vs baseline: 1.8953x; 1.0066x over previous
#include <cuda_runtime.h>
#include <cuda_bf16.h>
#include <cstdint>

typedef unsigned long long u64;

// ---------------------------------------------------------------------------
// dilate_block — round 16: R15 + compressed valid-tap loop:
//   iterate only over taps whose warp has >=1 valid neighbor (bitmask walk);
//   every feature load overlaps a real MMA burst; dead taps cost nothing.
// ---------------------------------------------------------------------------

static constexpr int MAXR = 640000;
static constexpr int MAXBLK = MAXR / 128 + 2;

__device__ __align__(16) float g_A [MAXR * 64];
__device__ __align__(16) float g_B [MAXR * 64];
__device__ __align__(16) float g_C [MAXR * 64];
__device__ __align__(16) float g_D [MAXR * 64];
__device__ __align__(16) float g_X1[MAXR * 64];
__device__ __align__(16) float g_X2[MAXR * 64];
__device__ __align__(16) float g_X3[MAXR * 64];
__device__ float g_pS[2 * MAXBLK * 64];
__device__ float g_pQ[2 * MAXBLK * 64];
__device__ float g_st[4 * 128];
__device__ unsigned g_tick[2];                          // zero-init, self-resetting
__device__ __align__(16) float g_Wt[3 * 4096];          // down_w packed (fp32 path)
__device__ __align__(16) uint32_t g_Wb[516096];         // conv weights, frag-major, hi/lo interleaved

// ---------------- helpers ----------------
__device__ __forceinline__ uint32_t smem_u32(const void* p) {
    uint32_t a;
    asm("{ .reg .u64 t; cvta.to.shared.u64 t, %1; cvt.u32.u64 %0, t; }" : "=r"(a) : "l"(p));
    return a;
}
__device__ __forceinline__ uint32_t cvt2(float lo, float hi) {
    uint32_t r;
    asm("cvt.rn.bf16x2.f32 %0, %1, %2;" : "=r"(r) : "f"(hi), "f"(lo));
    return r;
}
__device__ __forceinline__ uint32_t lds32(uint32_t a) {
    uint32_t v;
    asm volatile("ld.shared.b32 %0, [%1];" : "=r"(v) : "r"(a));
    return v;
}
__device__ __forceinline__ void st32(uint32_t a, uint32_t v) {
    asm volatile("st.shared.b32 [%0], %1;" :: "r"(a), "r"(v));
}
__device__ __forceinline__ void mma_bf16(float d[4], const uint32_t a[4], const uint32_t b[2]) {
    asm volatile(
        "mma.sync.aligned.m16n8k16.row.col.f32.bf16.bf16.f32 "
        "{%0,%1,%2,%3}, {%4,%5,%6,%7}, {%8,%9}, {%0,%1,%2,%3};"
        : "+f"(d[0]), "+f"(d[1]), "+f"(d[2]), "+f"(d[3])
        : "r"(a[0]), "r"(a[1]), "r"(a[2]), "r"(a[3]), "r"(b[0]), "r"(b[1]));
}
__device__ __forceinline__ u64 ffma2(u64 a, u64 b, u64 c) {
    u64 d;
    asm("fma.rn.f32x2 %0, %1, %2, %3;" : "=l"(d) : "l"(a), "l"(b), "l"(c));
    return d;
}

// ---------------------------------------------------------------------------
// weight prep: fp32 [K][CIN][64] -> per tap [kt][nt(8)][lane(32)][hi0,hi1,lo0,lo1]
// ---------------------------------------------------------------------------
struct WPtrs { const float* p[13]; };

__global__ void __launch_bounds__(256)
wprep(WPtrs w, uint32_t* __restrict__ dst)
{
    const int nT[13]   = {9,9,9,9,27,9,9,9,9,9,9,9,9};
    const int cinA[13] = {32,64,32,64,64,64,64,64,64,64,64,64,64};
    const int offW[13] = {0,18432,55296,73728,110592,221184,258048,294912,
                          331776,368640,405504,442368,479232};
    int b = blockIdx.x, c = 0;
    while (b >= nT[c]) { b -= nT[c]; ++c; }
    const int CIN = cinA[c];
    const int KT = CIN / 16;
    const float* src = w.p[c] + (size_t)b * CIN * 64;
    uint16_t* tap = reinterpret_cast<uint16_t*>(dst + offW[c] + (size_t)b * (KT * 1024));
    for (int e = threadIdx.x; e < CIN * 64; e += 256) {
        const int ci = e >> 6, co = e & 63;
        const float x = src[e];
        __nv_bfloat16 hb = __float2bfloat16(x);
        __nv_bfloat16 lb = __float2bfloat16(x - __bfloat162float(hb));
        const int kt = ci >> 4, ck = (ci & 15) >> 1, j = ci & 1;
        const int regb = (ck >= 4) ? 1 : 0;
        const int tt = ck & 3, nt = co >> 3, gg = co & 7;
        const int word = (((kt * 8 + nt) * 32 + (gg * 4 + tt)) * 4) + regb;  // hi at +0/+1
        tap[word * 2 + j]       = *reinterpret_cast<unsigned short*>(&hb);
        tap[(word + 2) * 2 + j] = *reinterpret_cast<unsigned short*>(&lb);   // lo at +2/+3
    }
}

__global__ void wtrans_down(const float* __restrict__ src, float* __restrict__ dst)
{
    const int k = blockIdx.x;
    for (int e = threadIdx.x; e < 4096; e += 256) {
        const int ci = e >> 6, co = e & 63;
        dst[k * 4096 + ((ci >> 2) * 64 + co) * 4 + (ci & 3)] = src[k * 4096 + e];
    }
}

// ---------------------------------------------------------------------------
// conv body: one 128-row tile per virtual block bid. Compressed valid-tap loop.
// ---------------------------------------------------------------------------
struct ConvArgs {
    const float* in;
    const int* nbr;
    const uint32_t* W;
    float* out;
    float* pS;
    float* pQ;
    float* st;
    const float* bn;
};

template <int KTILES, int KTAPS, bool STATS, bool BN>
__device__ __forceinline__ void conv_body(
    const ConvArgs a, int nIn, int nOut,
    unsigned* tick, int bid, int nBlocks, char* smem)
{
    constexpr int CIN = KTILES * 16;
    constexpr int TAPW = KTILES * 1024;
    constexpr int ATERM_BYTES = KTILES * 4 * 33 * 4;
    constexpr int ABUF_BYTES = 2 * ATERM_BYTES;
    constexpr int NF4 = CIN / 8;

    __shared__ float redS[8][64];
    __shared__ float redQ[8][64];
    __shared__ float s_st[128];
    __shared__ unsigned s_last;

    const uint32_t abase = smem_u32(smem);
    const int t = threadIdx.x;
    const int w = t >> 5;
    const int l = t & 31;
    const int rowBase = bid * 128 + w * 16;

    if (BN) {
        if (t < 128) s_st[t] = a.bn[t];
        __syncthreads();
    }

    const uint32_t abuf0 = abase + (uint32_t)(w * 2 + 0) * ABUF_BYTES;
    const uint32_t abuf1 = abase + (uint32_t)(w * 2 + 1) * ABUF_BYTES;

    const int gr = l >> 1;
    const int part = l & 1;
    const int grow = rowBase + gr;
    const bool rowOK = (grow < nOut);

    float4 pf[NF4];
    auto getj = [&](int k) -> int {
        return rowOK ? __ldg(&a.nbr[(size_t)k * nOut + grow]) : nIn;
    };
    auto loaddata = [&](int j) {
        if (j < nIn) {
            const float4* s = reinterpret_cast<const float4*>(a.in + (size_t)j * CIN) + part * NF4;
#pragma unroll
            for (int i = 0; i < NF4; ++i) {
                float4 v = s[i];
                if (BN) {
                    const int c4 = (part * NF4 + i) * 4;
                    v.x = (v.x - s_st[c4 + 0]) * s_st[64 + c4 + 0];
                    v.y = (v.y - s_st[c4 + 1]) * s_st[64 + c4 + 1];
                    v.z = (v.z - s_st[c4 + 2]) * s_st[64 + c4 + 2];
                    v.w = (v.w - s_st[c4 + 3]) * s_st[64 + c4 + 3];
                    v.x = v.x > 0.f ? v.x : 0.01f * v.x;
                    v.y = v.y > 0.f ? v.y : 0.01f * v.y;
                    v.z = v.z > 0.f ? v.z : 0.01f * v.z;
                    v.w = v.w > 0.f ? v.w : 0.01f * v.w;
                }
                pf[i] = v;
            }
        } else {
#pragma unroll
            for (int i = 0; i < NF4; ++i) pf[i] = make_float4(0.f, 0.f, 0.f, 0.f);
        }
    };
    auto convert_sts = [&](uint32_t buf) {
#pragma unroll
        for (int i = 0; i < NF4; ++i) {
            const int kt = (KTILES == 4) ? (part * 2 + (i >> 2)) : part;
            const int regb = ((gr >> 3) & 1) | ((i & 2) ? 2 : 0);
            const int lane0 = ((gr & 7) << 2) + ((i & 1) << 1);
            const uint32_t w0 = (uint32_t)(((kt * 4 + regb) * 33 + lane0) * 4);
            const float4 x = pf[i];
            const uint32_t h0 = cvt2(x.x, x.y);
            const uint32_t h1 = cvt2(x.z, x.w);
            const float l0 = x.x - __uint_as_float(h0 << 16);
            const float l1 = x.y - __uint_as_float(h0 & 0xFFFF0000u);
            const float l2 = x.z - __uint_as_float(h1 << 16);
            const float l3 = x.w - __uint_as_float(h1 & 0xFFFF0000u);
            const uint32_t q0 = cvt2(l0, l1);
            const uint32_t q1 = cvt2(l2, l3);
            st32(buf + w0, h0);
            st32(buf + w0 + 4, h1);
            st32(buf + ATERM_BYTES + w0, q0);
            st32(buf + ATERM_BYTES + w0 + 4, q1);
        }
    };
    auto mma_tap = [&](int k, uint32_t cur, float acc[8][4]) {
        const uint32_t* wtap = a.W + (size_t)k * TAPW;
#pragma unroll
        for (int kt = 0; kt < KTILES; ++kt) {
            uint32_t ah[4], al[4];
#pragma unroll
            for (int j = 0; j < 4; ++j) {
                const uint32_t ao = (uint32_t)(((kt * 4 + j) * 33 + l) * 4);
                ah[j] = lds32(cur + ao);
                al[j] = lds32(cur + ATERM_BYTES + ao);
            }
#pragma unroll
            for (int nt = 0; nt < 8; ++nt) {
                const uint32_t widx = ((kt * 8 + nt) * 32 + l) * 4;
                const uint4 bv = __ldg(reinterpret_cast<const uint4*>(a.W + (size_t)k * TAPW + widx));
                uint32_t bh[2] = {bv.x, bv.y};
                uint32_t bl[2] = {bv.z, bv.w};
                mma_bf16(acc[nt], ah, bh);
                mma_bf16(acc[nt], al, bh);
                mma_bf16(acc[nt], ah, bl);
            }
        }
        (void)wtap;
    };

    // ---- prologue: batched validity mask (chunks of 9 -> one latency hit) ----
    unsigned vmask = 0;
#pragma unroll
    for (int c0 = 0; c0 < KTAPS; c0 += 9) {
        int jj[9];
#pragma unroll
        for (int i = 0; i < 9; ++i)
            if (c0 + i < KTAPS) jj[i] = getj(c0 + i);
#pragma unroll
        for (int i = 0; i < 9; ++i)
            if (c0 + i < KTAPS)
                if (__ballot_sync(0xFFFFFFFFu, jj[i] < nIn)) vmask |= 1u << (c0 + i);
    }

    float acc[8][4];
#pragma unroll
    for (int nt = 0; nt < 8; ++nt)
#pragma unroll
        for (int j = 0; j < 4; ++j) acc[nt][j] = 0.f;

    // ---- compressed valid-tap pipeline ----
    unsigned m = vmask;
    int kcur = -1;
    if (m) { kcur = __ffs(m) - 1; m &= m - 1; }
    if (kcur >= 0) {
        loaddata(getj(kcur));       // nbr line L1-resident from prologue
        convert_sts(abuf0);
    }
    __syncwarp();
    uint32_t bufCur = abuf0, bufNxt = abuf1;
    while (kcur >= 0) {
        int knxt = -1;
        if (m) { knxt = __ffs(m) - 1; m &= m - 1; }
        if (knxt >= 0) loaddata(getj(knxt));
        mma_tap(kcur, bufCur, acc);
        if (knxt >= 0) convert_sts(bufNxt);
        __syncwarp();
        const uint32_t tmp = bufCur; bufCur = bufNxt; bufNxt = tmp;
        kcur = knxt;
    }

    // ---- epilogue ----
    const int dg = l >> 2, dt = l & 3;
    const int row0 = rowBase + dg;
    const int row1 = row0 + 8;
    if (row0 < nOut) {
        float* o = a.out + (size_t)row0 * 64 + dt * 2;
#pragma unroll
        for (int nt = 0; nt < 8; ++nt)
            *reinterpret_cast<float2*>(o + nt * 8) = make_float2(acc[nt][0], acc[nt][1]);
    }
    if (row1 < nOut) {
        float* o = a.out + (size_t)row1 * 64 + dt * 2;
#pragma unroll
        for (int nt = 0; nt < 8; ++nt)
            *reinterpret_cast<float2*>(o + nt * 8) = make_float2(acc[nt][2], acc[nt][3]);
    }

    if (STATS) {
#pragma unroll
        for (int nt = 0; nt < 8; ++nt) {
#pragma unroll
            for (int j = 0; j < 2; ++j) {
                float ss = acc[nt][j] + acc[nt][j + 2];
                float qq = acc[nt][j] * acc[nt][j] + acc[nt][j + 2] * acc[nt][j + 2];
                ss += __shfl_xor_sync(0xFFFFFFFFu, ss, 4);
                qq += __shfl_xor_sync(0xFFFFFFFFu, qq, 4);
                ss += __shfl_xor_sync(0xFFFFFFFFu, ss, 8);
                qq += __shfl_xor_sync(0xFFFFFFFFu, qq, 8);
                ss += __shfl_xor_sync(0xFFFFFFFFu, ss, 16);
                qq += __shfl_xor_sync(0xFFFFFFFFu, qq, 16);
                if (l < 4) {
                    redS[w][nt * 8 + l * 2 + j] = ss;
                    redQ[w][nt * 8 + l * 2 + j] = qq;
                }
            }
        }
        __syncthreads();
        if (t < 64) {
            float s = 0.f, q = 0.f;
#pragma unroll
            for (int ww = 0; ww < 8; ++ww) { s += redS[ww][t]; q += redQ[ww][t]; }
            a.pS[(size_t)bid * 64 + t] = s;
            a.pQ[(size_t)bid * 64 + t] = q;
        }
        __syncthreads();
        __threadfence();
        if (t == 0) s_last = (atomicAdd(tick, 1u) == (unsigned)nBlocks - 1u) ? 1u : 0u;
        __syncthreads();
        if (s_last) {
            __threadfence();
            const int co = t & 63, sub = t >> 6;
            float s = 0.f, q = 0.f;
            for (int b = sub; b < nBlocks; b += 4) {
                s += a.pS[(size_t)b * 64 + co];
                q += a.pQ[(size_t)b * 64 + co];
            }
            redS[sub][co] = s;
            redQ[sub][co] = q;
            __syncthreads();
            if (t < 64) {
                const float S = (redS[0][t] + redS[1][t]) + (redS[2][t] + redS[3][t]);
                const float Q = (redQ[0][t] + redQ[1][t]) + (redQ[2][t] + redQ[3][t]);
                const float inv = 1.0f / (float)nOut;
                const float m2 = S * inv;
                const float var = Q * inv - m2 * m2;
                a.st[t] = m2;
                a.st[64 + t] = rsqrtf(var + 1e-5f);
            }
            __syncthreads();
            if (t == 0) *tick = 0u;
        }
    }
}

// single conv (pool)
template <int KTILES, int KTAPS>
__global__ void __launch_bounds__(256, 2)
mma_conv_single(ConvArgs a, int nIn, int nOut)
{
    extern __shared__ __align__(16) char smem[];
    conv_body<KTILES, KTAPS, false, false>(a, nIn, nOut, nullptr,
                                           blockIdx.x, gridDim.x, smem);
}

// dual conv: blocks [0,gHalf) run a0, [gHalf,2*gHalf) run a1; both emit stats
template <int KTILES, int KTAPS, bool BN>
__global__ void __launch_bounds__(256, 2)
mma_conv_dual(ConvArgs a0, ConvArgs a1, int nIn, int nOut, int gHalf, unsigned* ticks)
{
    extern __shared__ __align__(16) char smem[];
    if (blockIdx.x < (unsigned)gHalf) {
        conv_body<KTILES, KTAPS, true, BN>(a0, nIn, nOut, &ticks[0],
                                           blockIdx.x, gHalf, smem);
    } else {
        conv_body<KTILES, KTAPS, true, BN>(a1, nIn, nOut, &ticks[1],
                                           blockIdx.x - gHalf, gHalf, smem);
    }
}

// ---------------------------------------------------------------------------
__global__ void combine_kernel(const float4* __restrict__ a, const float* __restrict__ sa,
                               const float4* __restrict__ b, const float* __restrict__ sb,
                               float4* __restrict__ o, long long n4)
{
    const long long i = (long long)blockIdx.x * blockDim.x + threadIdx.x;
    if (i >= n4) return;
    const int c = ((int)(i & 15)) * 4;
    float4 va = a[i];
    float4 vb = b[i];
    float4 r;
    float x;
    x = (va.x - sa[c + 0]) * sa[64 + c + 0]; x = x > 0.f ? x : 0.01f * x; r.x = x;
    x = (va.y - sa[c + 1]) * sa[64 + c + 1]; x = x > 0.f ? x : 0.01f * x; r.y = x;
    x = (va.z - sa[c + 2]) * sa[64 + c + 2]; x = x > 0.f ? x : 0.01f * x; r.z = x;
    x = (va.w - sa[c + 3]) * sa[64 + c + 3]; x = x > 0.f ? x : 0.01f * x; r.w = x;
    x = (vb.x - sb[c + 0]) * sb[64 + c + 0]; x = x > 0.f ? x : 0.01f * x; r.x += x;
    x = (vb.y - sb[c + 1]) * sb[64 + c + 1]; x = x > 0.f ? x : 0.01f * x; r.y += x;
    x = (vb.z - sb[c + 2]) * sb[64 + c + 2]; x = x > 0.f ? x : 0.01f * x; r.z += x;
    x = (vb.w - sb[c + 3]) * sb[64 + c + 3]; x = x > 0.f ? x : 0.01f * x; r.w += x;
    o[i] = r;
}

// out[m] = [x1 | x2 | x3] @ down_w  (fp32 FFMA2 path, warp-autonomous)
__global__ void __launch_bounds__(256)
final_kernel(const float* __restrict__ X1, const float* __restrict__ X2,
             const float* __restrict__ X3, const float* __restrict__ Wp,
             float* __restrict__ out, int M)
{
    __shared__ __align__(16) float buf[8][2][8][64];
    const int t = threadIdx.x;
    const int w = t >> 5;
    const int l = t & 31;
    const int rowBase = (blockIdx.x * 8 + w) * 8;
    const int gr = l >> 2;
    const int gp = l & 3;
    const int grow = rowBase + gr;
    const bool rowOK = (grow < M);

    const float* srcs[3] = {X1, X2, X3};
    auto prefetch = [&](int s, int b) {
        const float* src = srcs[s] + (size_t)(rowOK ? grow : 0) * 64;
        const int sz = rowOK ? 16 : 0;
        const uint32_t dbase = (uint32_t)__cvta_generic_to_shared(&buf[w][b][gr][0]);
#pragma unroll
        for (int i = 0; i < 4; ++i) {
            const int c4 = gp + 4 * i;
            asm volatile("cp.async.ca.shared.global [%0], [%1], 16, %2;\n"
                         :: "r"(dbase + c4 * 16), "l"(src + c4 * 4), "r"(sz));
        }
        asm volatile("cp.async.commit_group;\n");
    };

    u64 accA[8], accB[8];
#pragma unroll
    for (int r = 0; r < 8; ++r) { accA[r] = 0ull; accB[r] = 0ull; }

    prefetch(0, 0);
    for (int s = 0; s < 3; ++s) {
        if (s + 1 < 3) {
            prefetch(s + 1, (s + 1) & 1);
            asm volatile("cp.async.wait_group 1;\n");
        } else {
            asm volatile("cp.async.wait_group 0;\n");
        }
        __syncwarp();
        const float* wk = Wp + (size_t)s * (64 * 64);
        const float* frow = &buf[w][s & 1][0][0];
#pragma unroll
        for (int q = 0; q < 16; ++q) {
            const ulonglong2 wa = *reinterpret_cast<const ulonglong2*>(wk + (q * 64 + l) * 4);
            const ulonglong2 wb = *reinterpret_cast<const ulonglong2*>(wk + (q * 64 + l + 32) * 4);
#pragma unroll
            for (int r = 0; r < 8; ++r) {
                const ulonglong2 s2 =
                    *reinterpret_cast<const ulonglong2*>(frow + r * 64 + q * 4);
                accA[r] = ffma2(s2.x, wa.x, accA[r]);
                accA[r] = ffma2(s2.y, wa.y, accA[r]);
                accB[r] = ffma2(s2.x, wb.x, accB[r]);
                accB[r] = ffma2(s2.y, wb.y, accB[r]);
            }
        }
        __syncwarp();
    }
#pragma unroll
    for (int r = 0; r < 8; ++r) {
        const int orow = rowBase + r;
        if (orow < M) {
            out[(size_t)orow * 64 + l] =
                __uint_as_float((unsigned)accA[r]) + __uint_as_float((unsigned)(accA[r] >> 32));
            out[(size_t)orow * 64 + l + 32] =
                __uint_as_float((unsigned)accB[r]) + __uint_as_float((unsigned)(accB[r] >> 32));
        }
    }
}

// ---------------------------------------------------------------------------
extern "C" void kernel_launch(void* const* d_in, const int* in_sizes, int n_in,
                              void* d_out, int out_size)
{
    const float* feats  = (const float*)d_in[0];
    const float* down_w = (const float*)d_in[14];
    const int* n331_1 = (const int*)d_in[15];
    const int* n313_1 = (const int*)d_in[16];
    const int* pool_n = (const int*)d_in[17];
    const int* n331_2 = (const int*)d_in[18];
    const int* n313_2 = (const int*)d_in[19];
    const int* n331_3 = (const int*)d_in[20];
    const int* n313_3 = (const int*)d_in[21];

    const int N = in_sizes[0] / 32;
    const int M = out_size / 64;

    float *A, *B, *C, *D, *X1, *X2, *X3, *pS, *pQ, *st, *Wt;
    uint32_t* Wb;
    unsigned* ticks;
    cudaGetSymbolAddress((void**)&A,  g_A);
    cudaGetSymbolAddress((void**)&B,  g_B);
    cudaGetSymbolAddress((void**)&C,  g_C);
    cudaGetSymbolAddress((void**)&D,  g_D);
    cudaGetSymbolAddress((void**)&X1, g_X1);
    cudaGetSymbolAddress((void**)&X2, g_X2);
    cudaGetSymbolAddress((void**)&X3, g_X3);
    cudaGetSymbolAddress((void**)&pS, g_pS);
    cudaGetSymbolAddress((void**)&pQ, g_pQ);
    cudaGetSymbolAddress((void**)&st, g_st);
    cudaGetSymbolAddress((void**)&Wt, g_Wt);
    cudaGetSymbolAddress((void**)&Wb, g_Wb);
    cudaGetSymbolAddress((void**)&ticks, g_tick);
    float* st0 = st;
    float* st1 = st + 128;
    float* st2 = st + 256;
    float* st3 = st + 384;
    float* pS1 = pS + (size_t)MAXBLK * 64;
    float* pQ1 = pQ + (size_t)MAXBLK * 64;

    const size_t o0 = 0;
    const size_t o1 = 18432;
    const size_t o2 = 55296;
    const size_t o3 = 73728;
    const size_t o4 = 110592;
    const size_t o5 = 221184;
    const size_t o6 = 258048;
    const size_t o7 = 294912;
    const size_t o8 = 331776;
    const size_t o9 = 368640;
    const size_t o10 = 405504;
    const size_t o11 = 442368;
    const size_t o12 = 479232;

    const int SM2 = 8 * 2 * (2 * 2 * 4 * 33 * 4);   // KTILES=2: 33792
    const int SM4 = 8 * 2 * (2 * 4 * 4 * 33 * 4);   // KTILES=4: 67584
    cudaFuncSetAttribute(mma_conv_dual<2, 9, false>,
                         cudaFuncAttributeMaxDynamicSharedMemorySize, SM2);
    cudaFuncSetAttribute(mma_conv_dual<4, 9, false>,
                         cudaFuncAttributeMaxDynamicSharedMemorySize, SM4);
    cudaFuncSetAttribute(mma_conv_dual<4, 9, true>,
                         cudaFuncAttributeMaxDynamicSharedMemorySize, SM4);
    cudaFuncSetAttribute(mma_conv_single<4, 27>,
                         cudaFuncAttributeMaxDynamicSharedMemorySize, SM4);

    WPtrs wp;
    for (int i = 0; i < 13; ++i) wp.p[i] = (const float*)d_in[1 + i];
    wprep<<<135, 256>>>(wp, Wb);
    wtrans_down<<<3, 256>>>(down_w, Wt);

    const int gN = (N + 127) / 128;
    const int gM = (M + 127) / 128;
    const long long n4N = (long long)N * 16;
    const long long n4M = (long long)M * 16;
    const int gbN = (int)((n4N + 255) / 256);
    const int gbM = (int)((n4M + 255) / 256);
    const int gMf = (M + 63) / 64;

    auto CA = [](const float* in, const int* nbr, const uint32_t* W, float* out,
                 float* ps, float* pq, float* stp, const float* bn) {
        ConvArgs a;
        a.in = in; a.nbr = nbr; a.W = W; a.out = out;
        a.pS = ps; a.pQ = pq; a.st = stp; a.bn = bn;
        return a;
    };

    // ---- block 1 (N rows, 32 -> 64) ----
    mma_conv_dual<2, 9, false><<<2 * gN, 256, SM2>>>(
        CA(feats, n331_1, Wb + o0, A, pS,  pQ,  st0, nullptr),
        CA(feats, n313_1, Wb + o2, C, pS1, pQ1, st2, nullptr),
        N, N, gN, ticks);
    mma_conv_dual<4, 9, true><<<2 * gN, 256, SM4>>>(
        CA(A, n313_1, Wb + o1, B, pS,  pQ,  st1, st0),
        CA(C, n331_1, Wb + o3, D, pS1, pQ1, st3, st2),
        N, N, gN, ticks);
    combine_kernel<<<gbN, 256>>>((const float4*)D, st3, (const float4*)B, st1,
                                 (float4*)C, n4N);

    // ---- pool (K=27): C (N rows) -> X1 (M rows) ----
    mma_conv_single<4, 27><<<gM, 256, SM4>>>(
        CA(C, pool_n, Wb + o4, X1, nullptr, nullptr, nullptr, nullptr), N, M);

    // ---- block 2 (M rows, dilation 2) ----
    mma_conv_dual<4, 9, false><<<2 * gM, 256, SM4>>>(
        CA(X1, n331_2, Wb + o5, A, pS,  pQ,  st0, nullptr),
        CA(X1, n313_2, Wb + o7, C, pS1, pQ1, st2, nullptr),
        M, M, gM, ticks);
    mma_conv_dual<4, 9, true><<<2 * gM, 256, SM4>>>(
        CA(A, n313_2, Wb + o6, B, pS,  pQ,  st1, st0),
        CA(C, n331_2, Wb + o8, D, pS1, pQ1, st3, st2),
        M, M, gM, ticks);
    combine_kernel<<<gbM, 256>>>((const float4*)D, st3, (const float4*)B, st1,
                                 (float4*)X2, n4M);

    // ---- block 3 (M rows, dilation 3) ----
    mma_conv_dual<4, 9, false><<<2 * gM, 256, SM4>>>(
        CA(X2, n331_3, Wb + o9,  A, pS,  pQ,  st0, nullptr),
        CA(X2, n313_3, Wb + o11, C, pS1, pQ1, st2, nullptr),
        M, M, gM, ticks);
    mma_conv_dual<4, 9, true><<<2 * gM, 256, SM4>>>(
        CA(A, n313_3, Wb + o10, B, pS,  pQ,  st1, st0),
        CA(C, n331_3, Wb + o12, D, pS1, pQ1, st3, st2),
        M, M, gM, ticks);
    combine_kernel<<<gbM, 256>>>((const float4*)D, st3, (const float4*)B, st1,
                                 (float4*)X3, n4M);

    // ---- final 1x1 fuse ----
    final_kernel<<<gMf, 256>>>(X1, X2, X3, Wt, (float*)d_out, M);
}